// round 12
// baseline (speedup 1.0000x reference)
#include <cuda_runtime.h>
#include <cuda_fp16.h>
#include <math.h>
#include <stdint.h>

// Problem constants
#define LQ    2048
#define BATCH 2
#define EMB   1024
#define NH    16
#define HD    64
#define SK    2048
#define BHn   32
#define MR    4096

// ---------------- scratch (device globals) ----------------
__device__ __half g_inh[3 * MR * EMB];              // fp16 q/k/v inputs (GEMM rows)
__device__ __half g_wh[3 * EMB * EMB];              // fp16 in_proj_weight
__device__ __half g_woh[EMB * EMB];                 // fp16 out_w
__device__ __half g_qh[BHn * LQ * HD];              // [bh][l][d], pre-scaled 1/16
__device__ __half g_kh[BHn * SK * HD];              // [bh][s][d]
__device__ __half g_vth[BHn * HD * SK];             // [bh][d][s]
__device__ __half g_attnh[(size_t)BHn * LQ * SK];   // 256 MB fp16 scores (avg only)
__device__ __half g_ctxh[MR * EMB];                 // attention out, (L,B,E) rows

// ---------------- helpers ----------------
__device__ __forceinline__ uint32_t f2h2(float a, float b) {
    half2 h = __floats2half2_rn(a, b);
    return *reinterpret_cast<uint32_t*>(&h);
}
__device__ __forceinline__ uint32_t smem_u32(const void* p) {
    return (uint32_t)__cvta_generic_to_shared(p);
}

#define LDSM4(R0,R1,R2,R3,ADDR) \
    asm volatile("ldmatrix.sync.aligned.m8n8.x4.shared.b16 {%0,%1,%2,%3}, [%4];" \
        : "=r"(R0), "=r"(R1), "=r"(R2), "=r"(R3) : "r"(ADDR))

#define MMAH(C,A,B0,B1) \
    asm volatile("mma.sync.aligned.m16n8k16.row.col.f32.f16.f16.f32 " \
        "{%0,%1,%2,%3},{%4,%5,%6,%7},{%8,%9},{%0,%1,%2,%3};" \
        : "+f"((C)[0]), "+f"((C)[1]), "+f"((C)[2]), "+f"((C)[3]) \
        : "r"((A)[0]), "r"((A)[1]), "r"((A)[2]), "r"((A)[3]), "r"(B0), "r"(B1))

#define CPA16(DST, SRC) \
    asm volatile("cp.async.ca.shared.global [%0], [%1], 16;" \
        :: "r"(DST), "l"(SRC) : "memory")
#define CPA_COMMIT() asm volatile("cp.async.commit_group;" ::: "memory")
#define CPA_WAIT0()  asm volatile("cp.async.wait_group 0;" ::: "memory")

// named barrier: 128 threads of one group
#define BARG(ID) asm volatile("bar.sync %0, 128;" :: "r"(ID) : "memory")

// sigmoid(2u) for a packed half2 u: 0.5*tanh(u) + 0.5  (Q pre-scaled by extra 0.5)
__device__ __forceinline__ uint32_t sig_h2(float a, float b) {
    uint32_t p = f2h2(a, b);
    asm("tanh.approx.f16x2 %0, %0;" : "+r"(p));
    const half2 H05 = __half2half2(__ushort_as_half(0x3800));
    half2 t = *reinterpret_cast<half2*>(&p);
    t = __hfma2(t, H05, H05);
    return *reinterpret_cast<uint32_t*>(&t);
}

// =====================================================================
// fp32 -> fp16 conversion kernels
// =====================================================================
__global__ __launch_bounds__(256) void k_f2h3(
    const float* __restrict__ s0, const float* __restrict__ s1,
    const float* __restrict__ s2, __half* __restrict__ d, int n8)
{
    const float* s = (blockIdx.y == 0) ? s0 : (blockIdx.y == 1) ? s1 : s2;
    __half* dp = d + (size_t)blockIdx.y * n8 * 8;
    const int i = blockIdx.x * 256 + threadIdx.x;
    if (i < n8) {
        const float4 a = ((const float4*)s)[2 * i];
        const float4 b = ((const float4*)s)[2 * i + 1];
        uint4 o;
        o.x = f2h2(a.x, a.y); o.y = f2h2(a.z, a.w);
        o.z = f2h2(b.x, b.y); o.w = f2h2(b.z, b.w);
        ((uint4*)dp)[i] = o;
    }
}

__global__ __launch_bounds__(256) void k_f2h(const float* __restrict__ s,
                                             __half* __restrict__ d, int n8)
{
    const int i = blockIdx.x * 256 + threadIdx.x;
    if (i < n8) {
        const float4 a = ((const float4*)s)[2 * i];
        const float4 b = ((const float4*)s)[2 * i + 1];
        uint4 o;
        o.x = f2h2(a.x, a.y); o.y = f2h2(a.z, a.w);
        o.z = f2h2(b.x, b.y); o.w = f2h2(b.z, b.w);
        ((uint4*)d)[i] = o;
    }
}

// =====================================================================
// cp.async GEMM core (R7 config): CTA 128x128, 128 thr, 4 warps (2x2),
// warp 64x64, BK=64 halves, 2-stage double buffer. smem: A0|A1|B0|B1.
// =====================================================================
__device__ __forceinline__ void gemm_cp(
    const __half* __restrict__ A, int lda,
    const __half* __restrict__ B, int ldb,
    int K, float (&acc)[4][8][4], char* smem)
{
    const uint32_t sb = smem_u32(smem);
    const int tid = threadIdx.x, lane = tid & 31, warp = tid >> 5;
    const int wm0 = (warp >> 1) * 64, wn0 = (warp & 1) * 64;

    const int ssw = (tid & 7) << 4;
    const __half* Ap = A + (size_t)tid * lda;
    const __half* Bp = B + (size_t)tid * ldb;

    const int arow = wm0 + (lane & 15), agh = lane >> 4, lsw = lane & 7;
    const int brow = wn0 + (lane & 7) + ((lane >> 4) << 3), bgh = (lane >> 3) & 1;
    const uint32_t aB0 = sb + (uint32_t)arow * 128;
    const uint32_t bB0 = sb + 32768u + (uint32_t)brow * 128;

#pragma unroll
    for (int mt = 0; mt < 4; mt++)
#pragma unroll
        for (int nt = 0; nt < 8; nt++)
#pragma unroll
            for (int c = 0; c < 4; c++) acc[mt][nt][c] = 0.0f;

    {
        const uint32_t ad = sb + (uint32_t)tid * 128;
        const uint32_t bd = sb + 32768u + (uint32_t)tid * 128;
#pragma unroll
        for (int g = 0; g < 8; g++) {
            CPA16(ad + (uint32_t)((g * 16) ^ ssw), Ap + g * 8);
            CPA16(bd + (uint32_t)((g * 16) ^ ssw), Bp + g * 8);
        }
        CPA_COMMIT();
    }

    const int iters = K >> 6;
    for (int it = 0; it < iters; it++) {
        CPA_WAIT0();
        __syncthreads();

        if (it + 1 < iters) {
            const __half* An = Ap + (it + 1) * 64;
            const __half* Bn = Bp + (it + 1) * 64;
            const uint32_t ad = sb + (uint32_t)(((it + 1) & 1) * 16384) + (uint32_t)tid * 128;
            const uint32_t bd = ad + 32768u;
#pragma unroll
            for (int g = 0; g < 8; g++) {
                CPA16(ad + (uint32_t)((g * 16) ^ ssw), An + g * 8);
                CPA16(bd + (uint32_t)((g * 16) ^ ssw), Bn + g * 8);
            }
            CPA_COMMIT();
        }

        const uint32_t aB = aB0 + (uint32_t)((it & 1) * 16384);
        const uint32_t bB = bB0 + (uint32_t)((it & 1) * 16384);
#pragma unroll
        for (int ss = 0; ss < 4; ss++) {
            const uint32_t offA = (uint32_t)(((2 * ss + agh) ^ lsw) << 4);
            const uint32_t offB = (uint32_t)(((2 * ss + bgh) ^ lsw) << 4);
            uint32_t af[4][4], bf[4][4];
#pragma unroll
            for (int mt = 0; mt < 4; mt++)
                LDSM4(af[mt][0], af[mt][1], af[mt][2], af[mt][3],
                      aB + (uint32_t)(mt * 2048) + offA);
#pragma unroll
            for (int bt = 0; bt < 4; bt++)
                LDSM4(bf[bt][0], bf[bt][1], bf[bt][2], bf[bt][3],
                      bB + (uint32_t)(bt * 2048) + offB);
#pragma unroll
            for (int mt = 0; mt < 4; mt++)
#pragma unroll
                for (int bt = 0; bt < 4; bt++) {
                    MMAH(acc[mt][2 * bt],     af[mt], bf[bt][0], bf[bt][1]);
                    MMAH(acc[mt][2 * bt + 1], af[mt], bf[bt][2], bf[bt][3]);
                }
        }
    }
}

#define PROJ_SMEM 65536

// =====================================================================
// in-projection: grid (8, 32, 3), 128 thr. Q scaled by 1/16.
// ALL outputs staged through smem -> coalesced 128B stores.
// =====================================================================
__global__ __launch_bounds__(128, 2) void k_inproj_cp(const float* __restrict__ bias)
{
    extern __shared__ char smem[];
    const int p = blockIdx.z;
    const int m0 = blockIdx.y * 128, n0 = blockIdx.x * 128;
    const __half* A = g_inh + (size_t)p * MR * EMB + (size_t)m0 * EMB;
    const __half* B = g_wh + (size_t)p * EMB * EMB + (size_t)n0 * EMB;
    const float* bp = bias + p * EMB;
    const float scale = (p == 0) ? 0.0625f : 1.0f;

    float acc[4][8][4];
    gemm_cp(A, EMB, B, EMB, EMB, acc, smem);

    const int lane = threadIdx.x & 31, warp = threadIdx.x >> 5;
    const int wm0 = (warp >> 1) * 64, wn0 = (warp & 1) * 64;

    if (p == 2) {
        // ---- V: transpose via smem, coalesced stores ----
        __syncthreads();
        __half* ts = (__half*)smem;
        const int STR = 130;
#pragma unroll
        for (int nt = 0; nt < 8; nt++) {
            const int c = wn0 + nt * 8 + 2 * (lane & 3);
            const float b0 = bp[n0 + c], b1 = bp[n0 + c + 1];
#pragma unroll
            for (int mt = 0; mt < 4; mt++) {
                const int r = wm0 + mt * 16 + (lane >> 2);
                *(half2*)&ts[r * STR + c] =
                    __floats2half2_rn(acc[mt][nt][0] + b0, acc[mt][nt][1] + b1);
                *(half2*)&ts[(r + 8) * STR + c] =
                    __floats2half2_rn(acc[mt][nt][2] + b0, acc[mt][nt][3] + b1);
            }
        }
        __syncthreads();
        const int t = threadIdx.x;
#pragma unroll
        for (int si = 0; si < 2; si++) {
            const int bb  = si;
            const int col = t;
            const int hg  = (n0 >> 6) + (col >> 6);
            const int d   = col & 63;
            __half buf[64];
#pragma unroll
            for (int li = 0; li < 64; li++)
                buf[li] = ts[(2 * li + bb) * STR + col];
            __half* dst = g_vth + ((size_t)(bb * NH + hg) * HD + d) * SK + (m0 >> 1);
#pragma unroll
            for (int g = 0; g < 8; g++)
                *(uint4*)(dst + g * 8) = *(uint4*)(buf + g * 8);
        }
        return;
    }

    // ---- Q / K: stage tile in smem, then one 128B row per thread/head ----
    __syncthreads();
    __half* ts = (__half*)smem;
    const int STR = 136;   // halves; 272B rows (16B aligned, odd 16B-group walk)
#pragma unroll
    for (int nt = 0; nt < 8; nt++) {
        const int c = wn0 + nt * 8 + 2 * (lane & 3);
        const float b0 = bp[n0 + c], b1 = bp[n0 + c + 1];
#pragma unroll
        for (int mt = 0; mt < 4; mt++) {
            const int r = wm0 + mt * 16 + (lane >> 2);
            *(half2*)&ts[r * STR + c] =
                __floats2half2_rn((acc[mt][nt][0] + b0) * scale,
                                  (acc[mt][nt][1] + b1) * scale);
            *(half2*)&ts[(r + 8) * STR + c] =
                __floats2half2_rn((acc[mt][nt][2] + b0) * scale,
                                  (acc[mt][nt][3] + b1) * scale);
        }
    }
    __syncthreads();
    {
        const int t = threadIdx.x;
        const int l = (m0 + t) >> 1, bb = (m0 + t) & 1;
#pragma unroll
        for (int hh = 0; hh < 2; hh++) {
            const int hg = (n0 >> 6) + hh;
            const int bh = bb * NH + hg;
            uint4 buf[8];
#pragma unroll
            for (int g = 0; g < 8; g++)
                buf[g] = *(uint4*)&ts[t * STR + hh * 64 + g * 8];
            __half* dst = (p == 0 ? g_qh : g_kh) + ((size_t)bh * LQ + l) * HD;
#pragma unroll
            for (int g = 0; g < 8; g++)
                *(uint4*)(dst + g * 8) = buf[g];
        }
    }
}

// =====================================================================
// out-projection: grid (8, 32), 128 thr
// =====================================================================
__global__ __launch_bounds__(128, 2) void k_outproj_cp(
    const float* __restrict__ bo, float* __restrict__ out)
{
    extern __shared__ char smem[];
    const int m0 = blockIdx.y * 128, n0 = blockIdx.x * 128;

    float acc[4][8][4];
    gemm_cp(g_ctxh + (size_t)m0 * EMB, EMB, g_woh + (size_t)n0 * EMB, EMB, EMB, acc, smem);

    const int lane = threadIdx.x & 31, warp = threadIdx.x >> 5;
    const int wm0 = (warp >> 1) * 64, wn0 = (warp & 1) * 64;

#pragma unroll
    for (int nt = 0; nt < 8; nt++) {
        const int c = n0 + wn0 + nt * 8 + 2 * (lane & 3);
        const float b0 = bo[c], b1 = bo[c + 1];
#pragma unroll
        for (int mt = 0; mt < 4; mt++) {
            const int r = m0 + wm0 + mt * 16 + (lane >> 2);
            *(float2*)&out[(size_t)r * EMB + c] =
                make_float2(acc[mt][nt][0] + b0, acc[mt][nt][1] + b1);
            *(float2*)&out[(size_t)(r + 8) * EMB + c] =
                make_float2(acc[mt][nt][2] + b0, acc[mt][nt][3] + b1);
        }
    }
}

// =====================================================================
// FUSED attention: CTA = (128 l-rows, bh), 256 thr = 2 groups x 4 warps.
// 2-stage K/V buffers; tanh-sigmoid; P@ones denoms; named barriers.
// attn store: P-smem -> global, de-swizzled chunk at LOGICAL offset.
// smem: Q @1024 (16K) | group g @17408+g*49152: K0|K1|V0|V1|P
// =====================================================================
#define AT_Q     1024
#define AT_G0    17408
#define AT_GSZ   49152
#define AT_VOFF  16384
#define AT_POFF  32768
#define ATTN_SMEM (AT_G0 + 2 * AT_GSZ)   // 115712

__global__ __launch_bounds__(256, 1) void k_attn()
{
    extern __shared__ char smem[];
    const uint32_t sb = smem_u32(smem);

    const int bh = blockIdx.y;
    const int l0 = blockIdx.x * 128;
    const int b = bh >> 4, h = bh & 15;
    const int tid = threadIdx.x, lane = tid & 31, warp = tid >> 5;
    const int wg = warp >> 2;
    const int wl = warp & 3;
    const int wm = (wl >> 1) * 64;
    const int wq = (wl & 1) * 32;
    const uint32_t gb = AT_G0 + (uint32_t)wg * AT_GSZ;
    const int lt = tid & 127;
    const int barid = 1 + wg;
    const uint32_t ONES = 0x3C003C00u;   // half2(1,1)

    // ---- Q staging ----
    {
        const int qr = tid >> 1, qg = (tid & 1) * 4;
        const int qsw = (qr & 7) << 4;
        const __half* qs = g_qh + ((size_t)bh * LQ + l0 + qr) * HD + qg * 8;
        const uint32_t qd = sb + AT_Q + (uint32_t)qr * 128;
#pragma unroll
        for (int gi = 0; gi < 4; gi++)
            CPA16(qd + (uint32_t)((((qg + gi) * 16)) ^ qsw), qs + gi * 8);
    }
    // K/V staging
    const int kvrow = lt >> 1, cg0 = (lt & 1) * 4;
    const int ksw = (kvrow & 7) << 4;
    const __half* kp = g_kh  + ((size_t)bh * SK + wg * 64 + kvrow) * HD + (lt & 1) * 32;
    const __half* vp = g_vth + ((size_t)bh * HD + kvrow) * SK + wg * 64 + (lt & 1) * 32;
    {
        const uint32_t kd = sb + gb + (uint32_t)kvrow * 128;
        const uint32_t vd = kd + AT_VOFF;
#pragma unroll
        for (int gi = 0; gi < 4; gi++) {
            CPA16(kd + (uint32_t)(((cg0 + gi) * 16) ^ ksw), kp + gi * 8);
            CPA16(vd + (uint32_t)(((cg0 + gi) * 16) ^ ksw), vp + gi * 8);
        }
        CPA_COMMIT();
    }

    // ---- ldmatrix addressing ----
    const int aRow = wm + (lane & 15), agh = lane >> 4, lsw = lane & 7;
    const int bRow = wq + (lane & 7) + ((lane >> 4) << 3), bgh = (lane >> 3) & 1;
    const uint32_t aQ = sb + AT_Q + (uint32_t)aRow * 128;
    const uint32_t aP = sb + gb + AT_POFF + (uint32_t)aRow * 128;
    const uint32_t bK0 = sb + gb + (uint32_t)bRow * 128;
    const uint32_t bV0 = bK0 + AT_VOFF;
    char* psm = smem + gb + AT_POFF;

    float acc_pv[4][4][4], acc_den[4][4];
#pragma unroll
    for (int mt = 0; mt < 4; mt++) {
#pragma unroll
        for (int c = 0; c < 4; c++) acc_den[mt][c] = 0.0f;
#pragma unroll
        for (int nt = 0; nt < 4; nt++)
#pragma unroll
            for (int c = 0; c < 4; c++) acc_pv[mt][nt][c] = 0.0f;
    }

    const int r0b = wm + (lane >> 2);
    const int c0b = wq + 2 * (lane & 3);
    const int psw = (lt & 7);   // swizzle of this thread's own P row
    __half* arow_base = g_attnh + ((size_t)bh * LQ + l0 + lt) * SK;

    for (int it = 0; it < 16; it++) {
        CPA_WAIT0();
        if (it == 0) __syncthreads();
        else BARG(barid);

        if (it < 15) {
            kp += (size_t)128 * HD;
            vp += 128;
            const uint32_t kd = sb + gb + (uint32_t)(((it + 1) & 1) * 8192)
                              + (uint32_t)kvrow * 128;
            const uint32_t vd = kd + AT_VOFF;
#pragma unroll
            for (int gi = 0; gi < 4; gi++) {
                CPA16(kd + (uint32_t)(((cg0 + gi) * 16) ^ ksw), kp + gi * 8);
                CPA16(vd + (uint32_t)(((cg0 + gi) * 16) ^ ksw), vp + gi * 8);
            }
            CPA_COMMIT();
        }

        const uint32_t bufo = (uint32_t)((it & 1) * 8192);
        const uint32_t bK = bK0 + bufo, bV = bV0 + bufo;

        // ---- QK^T (K=64) ----
        float acc_qk[4][4][4];
#pragma unroll
        for (int mt = 0; mt < 4; mt++)
#pragma unroll
            for (int nt = 0; nt < 4; nt++)
#pragma unroll
                for (int c = 0; c < 4; c++) acc_qk[mt][nt][c] = 0.0f;

#pragma unroll
        for (int ss = 0; ss < 4; ss++) {
            const uint32_t offA = (uint32_t)(((2 * ss + agh) ^ lsw) << 4);
            const uint32_t offB = (uint32_t)(((2 * ss + bgh) ^ lsw) << 4);
            uint32_t af[4][4], bf[2][4];
#pragma unroll
            for (int mt = 0; mt < 4; mt++)
                LDSM4(af[mt][0], af[mt][1], af[mt][2], af[mt][3],
                      aQ + (uint32_t)(mt * 2048) + offA);
            LDSM4(bf[0][0], bf[0][1], bf[0][2], bf[0][3], bK + offB);
            LDSM4(bf[1][0], bf[1][1], bf[1][2], bf[1][3], bK + 2048u + offB);
#pragma unroll
            for (int mt = 0; mt < 4; mt++) {
                MMAH(acc_qk[mt][0], af[mt], bf[0][0], bf[0][1]);
                MMAH(acc_qk[mt][1], af[mt], bf[0][2], bf[0][3]);
                MMAH(acc_qk[mt][2], af[mt], bf[1][0], bf[1][1]);
                MMAH(acc_qk[mt][3], af[mt], bf[1][2], bf[1][3]);
            }
        }

        // ---- sigmoid epilogue: P smem only ----
#pragma unroll
        for (int mt = 0; mt < 4; mt++) {
            const int r0 = r0b + mt * 16;
            const int rsw = (r0 & 7);
#pragma unroll
            for (int nt = 0; nt < 4; nt++) {
                const int c0 = c0b + nt * 8;
                const uint32_t p01 = sig_h2(acc_qk[mt][nt][0], acc_qk[mt][nt][1]);
                const uint32_t p23 = sig_h2(acc_qk[mt][nt][2], acc_qk[mt][nt][3]);
                const int goff = (((c0 >> 3) ^ rsw) << 4) + ((c0 & 7) << 1);
                *(uint32_t*)(psm + r0 * 128 + goff) = p01;
                *(uint32_t*)(psm + (r0 + 8) * 128 + goff) = p23;
            }
        }
        BARG(barid);   // P ready (group-local)

        // ---- coalesced attn store: thread lt owns P row lt ----
        // chunk at physical ((g^psw)<<4) holds LOGICAL cols g*8..g*8+7
        {
            const int s0 = (2 * it + wg) * 64;
            __half* dst = arow_base + s0;
#pragma unroll
            for (int g = 0; g < 8; g++) {
                const uint4 v = *(uint4*)(psm + lt * 128 + ((g ^ psw) << 4));
                *(uint4*)(dst + g * 8) = v;
            }
        }

        // ---- P @ V^T (K=64) + P @ ones (denominators) ----
#pragma unroll
        for (int ss = 0; ss < 4; ss++) {
            const uint32_t offA = (uint32_t)(((2 * ss + agh) ^ lsw) << 4);
            const uint32_t offB = (uint32_t)(((2 * ss + bgh) ^ lsw) << 4);
            uint32_t af[4][4], bf[2][4];
#pragma unroll
            for (int mt = 0; mt < 4; mt++)
                LDSM4(af[mt][0], af[mt][1], af[mt][2], af[mt][3],
                      aP + (uint32_t)(mt * 2048) + offA);
            LDSM4(bf[0][0], bf[0][1], bf[0][2], bf[0][3], bV + offB);
            LDSM4(bf[1][0], bf[1][1], bf[1][2], bf[1][3], bV + 2048u + offB);
#pragma unroll
            for (int mt = 0; mt < 4; mt++) {
                MMAH(acc_pv[mt][0], af[mt], bf[0][0], bf[0][1]);
                MMAH(acc_pv[mt][1], af[mt], bf[0][2], bf[0][3]);
                MMAH(acc_pv[mt][2], af[mt], bf[1][0], bf[1][1]);
                MMAH(acc_pv[mt][3], af[mt], bf[1][2], bf[1][3]);
                MMAH(acc_den[mt],   af[mt], ONES, ONES);
            }
        }
    }

    // ---- cross-group merge: PV + den via padded smem ----
    __syncthreads();
    float* scr = (float*)(smem + AT_G0 + AT_GSZ);   // 128 x 73 floats
    if (tid >= 128) {
        const int t = tid - 128;
#pragma unroll
        for (int mt = 0; mt < 4; mt++) {
#pragma unroll
            for (int nt = 0; nt < 4; nt++)
#pragma unroll
                for (int c = 0; c < 4; c++)
                    scr[t * 73 + (mt * 4 + nt) * 4 + c] = acc_pv[mt][nt][c];
            scr[t * 73 + 64 + mt * 2]     = acc_den[mt][0];
            scr[t * 73 + 64 + mt * 2 + 1] = acc_den[mt][2];
        }
    }
    __syncthreads();
    if (tid < 128) {
#pragma unroll
        for (int mt = 0; mt < 4; mt++) {
            const int rl = wm + mt * 16 + (lane >> 2);
            const float den0 = acc_den[mt][0] + scr[tid * 73 + 64 + mt * 2];
            const float den1 = acc_den[mt][2] + scr[tid * 73 + 64 + mt * 2 + 1];
            const float inv0 = __fdividef(1.0f, den0 + 1e-4f);
            const float inv1 = __fdividef(1.0f, den1 + 1e-4f);
            const int l = l0 + rl;
#pragma unroll
            for (int nt = 0; nt < 4; nt++) {
                const int c = wq + nt * 8 + 2 * (lane & 3);
                const int si = tid * 73 + (mt * 4 + nt) * 4;
                const float o0 = (acc_pv[mt][nt][0] + scr[si + 0]) * inv0;
                const float o1 = (acc_pv[mt][nt][1] + scr[si + 1]) * inv0;
                const float o2 = (acc_pv[mt][nt][2] + scr[si + 2]) * inv1;
                const float o3 = (acc_pv[mt][nt][3] + scr[si + 3]) * inv1;
                *(half2*)&g_ctxh[(size_t)(l * BATCH + b) * EMB + h * HD + c] =
                    __floats2half2_rn(o0, o1);
                *(half2*)&g_ctxh[(size_t)((l + 8) * BATCH + b) * EMB + h * HD + c] =
                    __floats2half2_rn(o2, o3);
            }
        }
    }
}

// =====================================================================
// avg_weights from fp16 attn: grid 4096, 256 thr
// =====================================================================
__global__ __launch_bounds__(256) void k_avg_h(float* __restrict__ outAvg)
{
    const size_t t = (size_t)blockIdx.x * 256 + threadIdx.x;
    const int s8 = (int)(t & (SK / 8 - 1));
    const int l  = (int)((t >> 8) & (LQ - 1));
    const int b  = (int)(t >> 19);
    float acc[8] = {0, 0, 0, 0, 0, 0, 0, 0};
#pragma unroll
    for (int h = 0; h < NH; h++) {
        const uint4 u = *(const uint4*)&g_attnh[((size_t)(b * NH + h) * LQ + l) * SK + s8 * 8];
        const half2* p = (const half2*)&u;
#pragma unroll
        for (int j = 0; j < 4; j++) {
            const float2 f = __half22float2(p[j]);
            acc[2 * j]     += f.x;
            acc[2 * j + 1] += f.y;
        }
    }
    float* o = outAvg + t * 8;
    const float inv = 1.0f / NH;
    *(float4*)o       = make_float4(acc[0] * inv, acc[1] * inv, acc[2] * inv, acc[3] * inv);
    *(float4*)(o + 4) = make_float4(acc[4] * inv, acc[5] * inv, acc[6] * inv, acc[7] * inv);
}

// =====================================================================
extern "C" void kernel_launch(void* const* d_in, const int* in_sizes, int n_in,
                              void* d_out, int out_size)
{
    (void)in_sizes; (void)n_in; (void)out_size;
    const float* q    = (const float*)d_in[0];
    const float* k    = (const float*)d_in[1];
    const float* v    = (const float*)d_in[2];
    const float* Wqkv = (const float*)d_in[3];
    const float* bqkv = (const float*)d_in[4];
    const float* Wo   = (const float*)d_in[5];
    const float* bo   = (const float*)d_in[6];
    float* out    = (float*)d_out;
    float* outAvg = out + (size_t)LQ * BATCH * EMB;

    cudaFuncSetAttribute(k_inproj_cp,  cudaFuncAttributeMaxDynamicSharedMemorySize, PROJ_SMEM);
    cudaFuncSetAttribute(k_outproj_cp, cudaFuncAttributeMaxDynamicSharedMemorySize, PROJ_SMEM);
    cudaFuncSetAttribute(k_attn,       cudaFuncAttributeMaxDynamicSharedMemorySize, ATTN_SMEM);

    __half* inh; __half* wh; __half* woh;
    cudaGetSymbolAddress((void**)&inh, g_inh);
    cudaGetSymbolAddress((void**)&wh,  g_wh);
    cudaGetSymbolAddress((void**)&woh, g_woh);

    const int nIn = MR * EMB / 8;          // 524288
    const int nW  = 3 * EMB * EMB / 8;     // 393216
    const int nWo = EMB * EMB / 8;         // 131072
    k_f2h3<<<dim3((nIn + 255) / 256, 3), 256>>>(q, k, v, inh, nIn);
    k_f2h<<<(nW + 255) / 256, 256>>>(Wqkv, wh, nW);
    k_f2h<<<(nWo + 255) / 256, 256>>>(Wo, woh, nWo);

    k_inproj_cp<<<dim3(EMB / 128, MR / 128, 3), 128, PROJ_SMEM>>>(bqkv);
    k_attn<<<dim3(LQ / 128, BHn), 256, ATTN_SMEM>>>();
    k_avg_h<<<4096, 256>>>(outAvg);
    k_outproj_cp<<<dim3(EMB / 128, MR / 128), 128, PROJ_SMEM>>>(bo, out);
}

// round 13
// speedup vs baseline: 1.0719x; 1.0719x over previous
#include <cuda_runtime.h>
#include <cuda_fp16.h>
#include <math.h>
#include <stdint.h>

// Problem constants
#define LQ    2048
#define BATCH 2
#define EMB   1024
#define NH    16
#define HD    64
#define SK    2048
#define BHn   32
#define MR    4096

// ---------------- scratch (device globals) ----------------
__device__ __half g_inh[3 * MR * EMB];              // fp16 q/k/v inputs (GEMM rows)
__device__ __half g_wh[3 * EMB * EMB];              // fp16 in_proj_weight
__device__ __half g_woh[EMB * EMB];                 // fp16 out_w
__device__ __half g_qh[BHn * LQ * HD];              // [bh][l][d], pre-scaled 1/16
__device__ __half g_kh[BHn * SK * HD];              // [bh][s][d]
__device__ __half g_vth[BHn * HD * SK];             // [bh][d][s]
__device__ __half g_attnh[(size_t)BHn * LQ * SK];   // 256 MB fp16 scores (avg only)
__device__ __half g_ctxh[MR * EMB];                 // attention out, (L,B,E) rows

// ---------------- helpers ----------------
__device__ __forceinline__ uint32_t f2h2(float a, float b) {
    half2 h = __floats2half2_rn(a, b);
    return *reinterpret_cast<uint32_t*>(&h);
}
__device__ __forceinline__ uint32_t smem_u32(const void* p) {
    return (uint32_t)__cvta_generic_to_shared(p);
}

#define LDSM4(R0,R1,R2,R3,ADDR) \
    asm volatile("ldmatrix.sync.aligned.m8n8.x4.shared.b16 {%0,%1,%2,%3}, [%4];" \
        : "=r"(R0), "=r"(R1), "=r"(R2), "=r"(R3) : "r"(ADDR))

#define MMAH(C,A,B0,B1) \
    asm volatile("mma.sync.aligned.m16n8k16.row.col.f32.f16.f16.f32 " \
        "{%0,%1,%2,%3},{%4,%5,%6,%7},{%8,%9},{%0,%1,%2,%3};" \
        : "+f"((C)[0]), "+f"((C)[1]), "+f"((C)[2]), "+f"((C)[3]) \
        : "r"((A)[0]), "r"((A)[1]), "r"((A)[2]), "r"((A)[3]), "r"(B0), "r"(B1))

#define CPA16(DST, SRC) \
    asm volatile("cp.async.ca.shared.global [%0], [%1], 16;" \
        :: "r"(DST), "l"(SRC) : "memory")
#define CPA_COMMIT() asm volatile("cp.async.commit_group;" ::: "memory")
#define CPA_WAIT0()  asm volatile("cp.async.wait_group 0;" ::: "memory")

// named barrier: 128 threads of one group
#define BARG(ID) asm volatile("bar.sync %0, 128;" :: "r"(ID) : "memory")

// sigmoid(2u) for a packed half2 u: 0.5*tanh(u) + 0.5  (Q pre-scaled by extra 0.5)
__device__ __forceinline__ uint32_t sig_h2(float a, float b) {
    uint32_t p = f2h2(a, b);
    asm("tanh.approx.f16x2 %0, %0;" : "+r"(p));
    const half2 H05 = __half2half2(__ushort_as_half(0x3800));
    half2 t = *reinterpret_cast<half2*>(&p);
    t = __hfma2(t, H05, H05);
    return *reinterpret_cast<uint32_t*>(&t);
}

// =====================================================================
// fp32 -> fp16 conversion kernels
// =====================================================================
__global__ __launch_bounds__(256) void k_f2h3(
    const float* __restrict__ s0, const float* __restrict__ s1,
    const float* __restrict__ s2, __half* __restrict__ d, int n8)
{
    const float* s = (blockIdx.y == 0) ? s0 : (blockIdx.y == 1) ? s1 : s2;
    __half* dp = d + (size_t)blockIdx.y * n8 * 8;
    const int i = blockIdx.x * 256 + threadIdx.x;
    if (i < n8) {
        const float4 a = ((const float4*)s)[2 * i];
        const float4 b = ((const float4*)s)[2 * i + 1];
        uint4 o;
        o.x = f2h2(a.x, a.y); o.y = f2h2(a.z, a.w);
        o.z = f2h2(b.x, b.y); o.w = f2h2(b.z, b.w);
        ((uint4*)dp)[i] = o;
    }
}

__global__ __launch_bounds__(256) void k_f2h(const float* __restrict__ s,
                                             __half* __restrict__ d, int n8)
{
    const int i = blockIdx.x * 256 + threadIdx.x;
    if (i < n8) {
        const float4 a = ((const float4*)s)[2 * i];
        const float4 b = ((const float4*)s)[2 * i + 1];
        uint4 o;
        o.x = f2h2(a.x, a.y); o.y = f2h2(a.z, a.w);
        o.z = f2h2(b.x, b.y); o.w = f2h2(b.z, b.w);
        ((uint4*)d)[i] = o;
    }
}

// =====================================================================
// cp.async GEMM core: CTA 128x128, 128 thr, 4 warps (2x2), warp 64x64,
// BK=64 halves, 2-stage double buffer. smem: A0|A1|B0|B1.
// =====================================================================
__device__ __forceinline__ void gemm_cp(
    const __half* __restrict__ A, int lda,
    const __half* __restrict__ B, int ldb,
    int K, float (&acc)[4][8][4], char* smem)
{
    const uint32_t sb = smem_u32(smem);
    const int tid = threadIdx.x, lane = tid & 31, warp = tid >> 5;
    const int wm0 = (warp >> 1) * 64, wn0 = (warp & 1) * 64;

    const int ssw = (tid & 7) << 4;
    const __half* Ap = A + (size_t)tid * lda;
    const __half* Bp = B + (size_t)tid * ldb;

    const int arow = wm0 + (lane & 15), agh = lane >> 4, lsw = lane & 7;
    const int brow = wn0 + (lane & 7) + ((lane >> 4) << 3), bgh = (lane >> 3) & 1;
    const uint32_t aB0 = sb + (uint32_t)arow * 128;
    const uint32_t bB0 = sb + 32768u + (uint32_t)brow * 128;

#pragma unroll
    for (int mt = 0; mt < 4; mt++)
#pragma unroll
        for (int nt = 0; nt < 8; nt++)
#pragma unroll
            for (int c = 0; c < 4; c++) acc[mt][nt][c] = 0.0f;

    {
        const uint32_t ad = sb + (uint32_t)tid * 128;
        const uint32_t bd = sb + 32768u + (uint32_t)tid * 128;
#pragma unroll
        for (int g = 0; g < 8; g++) {
            CPA16(ad + (uint32_t)((g * 16) ^ ssw), Ap + g * 8);
            CPA16(bd + (uint32_t)((g * 16) ^ ssw), Bp + g * 8);
        }
        CPA_COMMIT();
    }

    const int iters = K >> 6;
    for (int it = 0; it < iters; it++) {
        CPA_WAIT0();
        __syncthreads();

        if (it + 1 < iters) {
            const __half* An = Ap + (it + 1) * 64;
            const __half* Bn = Bp + (it + 1) * 64;
            const uint32_t ad = sb + (uint32_t)(((it + 1) & 1) * 16384) + (uint32_t)tid * 128;
            const uint32_t bd = ad + 32768u;
#pragma unroll
            for (int g = 0; g < 8; g++) {
                CPA16(ad + (uint32_t)((g * 16) ^ ssw), An + g * 8);
                CPA16(bd + (uint32_t)((g * 16) ^ ssw), Bn + g * 8);
            }
            CPA_COMMIT();
        }

        const uint32_t aB = aB0 + (uint32_t)((it & 1) * 16384);
        const uint32_t bB = bB0 + (uint32_t)((it & 1) * 16384);
#pragma unroll
        for (int ss = 0; ss < 4; ss++) {
            const uint32_t offA = (uint32_t)(((2 * ss + agh) ^ lsw) << 4);
            const uint32_t offB = (uint32_t)(((2 * ss + bgh) ^ lsw) << 4);
            uint32_t af[4][4], bf[4][4];
#pragma unroll
            for (int mt = 0; mt < 4; mt++)
                LDSM4(af[mt][0], af[mt][1], af[mt][2], af[mt][3],
                      aB + (uint32_t)(mt * 2048) + offA);
#pragma unroll
            for (int bt = 0; bt < 4; bt++)
                LDSM4(bf[bt][0], bf[bt][1], bf[bt][2], bf[bt][3],
                      bB + (uint32_t)(bt * 2048) + offB);
#pragma unroll
            for (int mt = 0; mt < 4; mt++)
#pragma unroll
                for (int bt = 0; bt < 4; bt++) {
                    MMAH(acc[mt][2 * bt],     af[mt], bf[bt][0], bf[bt][1]);
                    MMAH(acc[mt][2 * bt + 1], af[mt], bf[bt][2], bf[bt][3]);
                }
        }
    }
}

#define PROJ_SMEM 65536

// =====================================================================
// in-projection: grid (8, 32, 3), 128 thr. Q scaled by 1/16.
// =====================================================================
__global__ __launch_bounds__(128, 2) void k_inproj_cp(const float* __restrict__ bias)
{
    extern __shared__ char smem[];
    const int p = blockIdx.z;
    const int m0 = blockIdx.y * 128, n0 = blockIdx.x * 128;
    const __half* A = g_inh + (size_t)p * MR * EMB + (size_t)m0 * EMB;
    const __half* B = g_wh + (size_t)p * EMB * EMB + (size_t)n0 * EMB;
    const float* bp = bias + p * EMB;
    const float scale = (p == 0) ? 0.0625f : 1.0f;

    float acc[4][8][4];
    gemm_cp(A, EMB, B, EMB, EMB, acc, smem);

    const int lane = threadIdx.x & 31, warp = threadIdx.x >> 5;
    const int wm0 = (warp >> 1) * 64, wn0 = (warp & 1) * 64;

    if (p == 2) {
        // ---- V: transpose via smem, coalesced stores ----
        __syncthreads();
        __half* ts = (__half*)smem;
        const int STR = 130;
#pragma unroll
        for (int nt = 0; nt < 8; nt++) {
            const int c = wn0 + nt * 8 + 2 * (lane & 3);
            const float b0 = bp[n0 + c], b1 = bp[n0 + c + 1];
#pragma unroll
            for (int mt = 0; mt < 4; mt++) {
                const int r = wm0 + mt * 16 + (lane >> 2);
                *(half2*)&ts[r * STR + c] =
                    __floats2half2_rn(acc[mt][nt][0] + b0, acc[mt][nt][1] + b1);
                *(half2*)&ts[(r + 8) * STR + c] =
                    __floats2half2_rn(acc[mt][nt][2] + b0, acc[mt][nt][3] + b1);
            }
        }
        __syncthreads();
        const int t = threadIdx.x;
#pragma unroll
        for (int si = 0; si < 2; si++) {
            const int bb  = si;
            const int col = t;
            const int hg  = (n0 >> 6) + (col >> 6);
            const int d   = col & 63;
            __half buf[64];
#pragma unroll
            for (int li = 0; li < 64; li++)
                buf[li] = ts[(2 * li + bb) * STR + col];
            __half* dst = g_vth + ((size_t)(bb * NH + hg) * HD + d) * SK + (m0 >> 1);
#pragma unroll
            for (int g = 0; g < 8; g++)
                *(uint4*)(dst + g * 8) = *(uint4*)(buf + g * 8);
        }
        return;
    }

    // ---- Q / K: stage tile in smem, then one 128B row per thread/head ----
    __syncthreads();
    __half* ts = (__half*)smem;
    const int STR = 136;
#pragma unroll
    for (int nt = 0; nt < 8; nt++) {
        const int c = wn0 + nt * 8 + 2 * (lane & 3);
        const float b0 = bp[n0 + c], b1 = bp[n0 + c + 1];
#pragma unroll
        for (int mt = 0; mt < 4; mt++) {
            const int r = wm0 + mt * 16 + (lane >> 2);
            *(half2*)&ts[r * STR + c] =
                __floats2half2_rn((acc[mt][nt][0] + b0) * scale,
                                  (acc[mt][nt][1] + b1) * scale);
            *(half2*)&ts[(r + 8) * STR + c] =
                __floats2half2_rn((acc[mt][nt][2] + b0) * scale,
                                  (acc[mt][nt][3] + b1) * scale);
        }
    }
    __syncthreads();
    {
        const int t = threadIdx.x;
        const int l = (m0 + t) >> 1, bb = (m0 + t) & 1;
#pragma unroll
        for (int hh = 0; hh < 2; hh++) {
            const int hg = (n0 >> 6) + hh;
            const int bh = bb * NH + hg;
            uint4 buf[8];
#pragma unroll
            for (int g = 0; g < 8; g++)
                buf[g] = *(uint4*)&ts[t * STR + hh * 64 + g * 8];
            __half* dst = (p == 0 ? g_qh : g_kh) + ((size_t)bh * LQ + l) * HD;
#pragma unroll
            for (int g = 0; g < 8; g++)
                *(uint4*)(dst + g * 8) = buf[g];
        }
    }
}

// =====================================================================
// out-projection: grid (8, 32), 128 thr
// =====================================================================
__global__ __launch_bounds__(128, 2) void k_outproj_cp(
    const float* __restrict__ bo, float* __restrict__ out)
{
    extern __shared__ char smem[];
    const int m0 = blockIdx.y * 128, n0 = blockIdx.x * 128;

    float acc[4][8][4];
    gemm_cp(g_ctxh + (size_t)m0 * EMB, EMB, g_woh + (size_t)n0 * EMB, EMB, EMB, acc, smem);

    const int lane = threadIdx.x & 31, warp = threadIdx.x >> 5;
    const int wm0 = (warp >> 1) * 64, wn0 = (warp & 1) * 64;

#pragma unroll
    for (int nt = 0; nt < 8; nt++) {
        const int c = n0 + wn0 + nt * 8 + 2 * (lane & 3);
        const float b0 = bo[c], b1 = bo[c + 1];
#pragma unroll
        for (int mt = 0; mt < 4; mt++) {
            const int r = m0 + wm0 + mt * 16 + (lane >> 2);
            *(float2*)&out[(size_t)r * EMB + c] =
                make_float2(acc[mt][nt][0] + b0, acc[mt][nt][1] + b1);
            *(float2*)&out[(size_t)(r + 8) * EMB + c] =
                make_float2(acc[mt][nt][2] + b0, acc[mt][nt][3] + b1);
        }
    }
}

// =====================================================================
// FUSED attention: CTA = (128 l-rows, bh), 256 thr = 2 groups x 4 warps.
// NEW: warp tile 32m x 64s -> each warp owns full s-range of its rows;
// P converts register-direct from QK accumulators to PV A-fragments
// (no P smem, no aP ldmatrix, one barrier per iter).
// smem: Q @1024 (16K) | group g @17408+g*32768: K0|K1 (16K) | V0|V1 (16K)
// =====================================================================
#define AT_Q     1024
#define AT_G0    17408
#define AT_GSZ   32768
#define AT_VOFF  16384
#define ATTN_SMEM (AT_G0 + 2 * AT_GSZ)   // 82944

__global__ __launch_bounds__(256, 1) void k_attn()
{
    extern __shared__ char smem[];
    const uint32_t sb = smem_u32(smem);

    const int bh = blockIdx.y;
    const int l0 = blockIdx.x * 128;
    const int b = bh >> 4, h = bh & 15;
    const int tid = threadIdx.x, lane = tid & 31, warp = tid >> 5;
    const int wg = warp >> 2;
    const int wl = warp & 3;
    const int wm = wl * 32;               // 32 rows per warp
    const uint32_t gb = AT_G0 + (uint32_t)wg * AT_GSZ;
    const int lt = tid & 127;
    const int barid = 1 + wg;
    const uint32_t ONES = 0x3C003C00u;    // half2(1,1)

    // ---- Q staging ----
    {
        const int qr = tid >> 1, qg = (tid & 1) * 4;
        const int qsw = (qr & 7) << 4;
        const __half* qs = g_qh + ((size_t)bh * LQ + l0 + qr) * HD + qg * 8;
        const uint32_t qd = sb + AT_Q + (uint32_t)qr * 128;
#pragma unroll
        for (int gi = 0; gi < 4; gi++)
            CPA16(qd + (uint32_t)((((qg + gi) * 16)) ^ qsw), qs + gi * 8);
    }
    // K/V staging (per group)
    const int kvrow = lt >> 1, cg0 = (lt & 1) * 4;
    const int ksw = (kvrow & 7) << 4;
    const __half* kp = g_kh  + ((size_t)bh * SK + wg * 64 + kvrow) * HD + (lt & 1) * 32;
    const __half* vp = g_vth + ((size_t)bh * HD + kvrow) * SK + wg * 64 + (lt & 1) * 32;
    {
        const uint32_t kd = sb + gb + (uint32_t)kvrow * 128;
        const uint32_t vd = kd + AT_VOFF;
#pragma unroll
        for (int gi = 0; gi < 4; gi++) {
            CPA16(kd + (uint32_t)(((cg0 + gi) * 16) ^ ksw), kp + gi * 8);
            CPA16(vd + (uint32_t)(((cg0 + gi) * 16) ^ ksw), vp + gi * 8);
        }
        CPA_COMMIT();
    }

    // ---- ldmatrix addressing ----
    const int aRow = wm + (lane & 15), agh = lane >> 4, lsw = lane & 7;
    const int bRow = (lane & 7) + ((lane >> 4) << 3), bgh = (lane >> 3) & 1;
    const uint32_t aQ  = sb + AT_Q + (uint32_t)aRow * 128;
    const uint32_t bK0 = sb + gb + (uint32_t)bRow * 128;
    const uint32_t bV0 = bK0 + AT_VOFF;

    float acc_pv[2][8][4], acc_den[2][4];
#pragma unroll
    for (int mt = 0; mt < 2; mt++) {
#pragma unroll
        for (int c = 0; c < 4; c++) acc_den[mt][c] = 0.0f;
#pragma unroll
        for (int nt = 0; nt < 8; nt++)
#pragma unroll
            for (int c = 0; c < 4; c++) acc_pv[mt][nt][c] = 0.0f;
    }

    const int r0b = wm + (lane >> 2);
    const int c0b = 2 * (lane & 3);

    for (int it = 0; it < 16; it++) {
        CPA_WAIT0();
        if (it == 0) __syncthreads();
        else BARG(barid);

        if (it < 15) {
            kp += (size_t)128 * HD;
            vp += 128;
            const uint32_t kd = sb + gb + (uint32_t)(((it + 1) & 1) * 8192)
                              + (uint32_t)kvrow * 128;
            const uint32_t vd = kd + AT_VOFF;
#pragma unroll
            for (int gi = 0; gi < 4; gi++) {
                CPA16(kd + (uint32_t)(((cg0 + gi) * 16) ^ ksw), kp + gi * 8);
                CPA16(vd + (uint32_t)(((cg0 + gi) * 16) ^ ksw), vp + gi * 8);
            }
            CPA_COMMIT();
        }

        const uint32_t bufo = (uint32_t)((it & 1) * 8192);
        const uint32_t bK = bK0 + bufo, bV = bV0 + bufo;

        // ---- QK^T: warp 32m x 64s, K=64 ----
        float acc_qk[2][8][4];
#pragma unroll
        for (int mt = 0; mt < 2; mt++)
#pragma unroll
            for (int nt = 0; nt < 8; nt++)
#pragma unroll
                for (int c = 0; c < 4; c++) acc_qk[mt][nt][c] = 0.0f;

#pragma unroll
        for (int ss = 0; ss < 4; ss++) {
            const uint32_t offA = (uint32_t)(((2 * ss + agh) ^ lsw) << 4);
            const uint32_t offB = (uint32_t)(((2 * ss + bgh) ^ lsw) << 4);
            uint32_t af[2][4], bf[4][4];
#pragma unroll
            for (int mt = 0; mt < 2; mt++)
                LDSM4(af[mt][0], af[mt][1], af[mt][2], af[mt][3],
                      aQ + (uint32_t)(mt * 2048) + offA);
#pragma unroll
            for (int bt = 0; bt < 4; bt++)
                LDSM4(bf[bt][0], bf[bt][1], bf[bt][2], bf[bt][3],
                      bK + (uint32_t)(bt * 2048) + offB);
#pragma unroll
            for (int mt = 0; mt < 2; mt++)
#pragma unroll
                for (int bt = 0; bt < 4; bt++) {
                    MMAH(acc_qk[mt][2 * bt],     af[mt], bf[bt][0], bf[bt][1]);
                    MMAH(acc_qk[mt][2 * bt + 1], af[mt], bf[bt][2], bf[bt][3]);
                }
        }

        // ---- sigmoid: register-direct pack to PV A-fragments + attn STG ----
        const int s0 = (2 * it + wg) * 64;
        uint32_t pa[2][4][4];   // [mt][k-chunk ss][frag reg]
#pragma unroll
        for (int mt = 0; mt < 2; mt++) {
            const int r0 = r0b + mt * 16;
            __half* ar0 = g_attnh + ((size_t)bh * LQ + l0 + r0) * SK + s0 + c0b;
            __half* ar1 = ar0 + 8 * SK;
#pragma unroll
            for (int nt = 0; nt < 8; nt++) {
                const uint32_t p01 = sig_h2(acc_qk[mt][nt][0], acc_qk[mt][nt][1]);
                const uint32_t p23 = sig_h2(acc_qk[mt][nt][2], acc_qk[mt][nt][3]);
                *(uint32_t*)(ar0 + nt * 8) = p01;
                *(uint32_t*)(ar1 + nt * 8) = p23;
                pa[mt][nt >> 1][(nt & 1) ? 2 : 0] = p01;
                pa[mt][nt >> 1][(nt & 1) ? 3 : 1] = p23;
            }
        }

        // ---- P @ V^T (A from registers) + P @ ones ----
#pragma unroll
        for (int ss = 0; ss < 4; ss++) {
            const uint32_t offB = (uint32_t)(((2 * ss + bgh) ^ lsw) << 4);
            uint32_t bf[4][4];
#pragma unroll
            for (int bt = 0; bt < 4; bt++)
                LDSM4(bf[bt][0], bf[bt][1], bf[bt][2], bf[bt][3],
                      bV + (uint32_t)(bt * 2048) + offB);
#pragma unroll
            for (int mt = 0; mt < 2; mt++) {
#pragma unroll
                for (int bt = 0; bt < 4; bt++) {
                    MMAH(acc_pv[mt][2 * bt],     pa[mt][ss], bf[bt][0], bf[bt][1]);
                    MMAH(acc_pv[mt][2 * bt + 1], pa[mt][ss], bf[bt][2], bf[bt][3]);
                }
                MMAH(acc_den[mt], pa[mt][ss], ONES, ONES);
            }
        }
    }

    // ---- cross-group merge: PV + den via padded smem ----
    __syncthreads();
    float* scr = (float*)(smem + AT_Q);   // 128 x 69 floats = 35.3KB (KV dead)
    if (tid >= 128) {
        const int t = tid - 128;
#pragma unroll
        for (int mt = 0; mt < 2; mt++) {
#pragma unroll
            for (int nt = 0; nt < 8; nt++)
#pragma unroll
                for (int c = 0; c < 4; c++)
                    scr[t * 69 + (mt * 8 + nt) * 4 + c] = acc_pv[mt][nt][c];
            scr[t * 69 + 64 + mt * 2]     = acc_den[mt][0];
            scr[t * 69 + 64 + mt * 2 + 1] = acc_den[mt][2];
        }
    }
    __syncthreads();
    if (tid < 128) {
#pragma unroll
        for (int mt = 0; mt < 2; mt++) {
            const int rl = wm + mt * 16 + (lane >> 2);
            const float den0 = acc_den[mt][0] + scr[tid * 69 + 64 + mt * 2];
            const float den1 = acc_den[mt][2] + scr[tid * 69 + 64 + mt * 2 + 1];
            const float inv0 = __fdividef(1.0f, den0 + 1e-4f);
            const float inv1 = __fdividef(1.0f, den1 + 1e-4f);
            const int l = l0 + rl;
#pragma unroll
            for (int nt = 0; nt < 8; nt++) {
                const int c = nt * 8 + 2 * (lane & 3);
                const int si = tid * 69 + (mt * 8 + nt) * 4;
                const float o0 = (acc_pv[mt][nt][0] + scr[si + 0]) * inv0;
                const float o1 = (acc_pv[mt][nt][1] + scr[si + 1]) * inv0;
                const float o2 = (acc_pv[mt][nt][2] + scr[si + 2]) * inv1;
                const float o3 = (acc_pv[mt][nt][3] + scr[si + 3]) * inv1;
                *(half2*)&g_ctxh[(size_t)(l * BATCH + b) * EMB + h * HD + c] =
                    __floats2half2_rn(o0, o1);
                *(half2*)&g_ctxh[(size_t)((l + 8) * BATCH + b) * EMB + h * HD + c] =
                    __floats2half2_rn(o2, o3);
            }
        }
    }
}

// =====================================================================
// avg_weights from fp16 attn: grid 4096, 256 thr
// =====================================================================
__global__ __launch_bounds__(256) void k_avg_h(float* __restrict__ outAvg)
{
    const size_t t = (size_t)blockIdx.x * 256 + threadIdx.x;
    const int s8 = (int)(t & (SK / 8 - 1));
    const int l  = (int)((t >> 8) & (LQ - 1));
    const int b  = (int)(t >> 19);
    float acc[8] = {0, 0, 0, 0, 0, 0, 0, 0};
#pragma unroll
    for (int h = 0; h < NH; h++) {
        const uint4 u = *(const uint4*)&g_attnh[((size_t)(b * NH + h) * LQ + l) * SK + s8 * 8];
        const half2* p = (const half2*)&u;
#pragma unroll
        for (int j = 0; j < 4; j++) {
            const float2 f = __half22float2(p[j]);
            acc[2 * j]     += f.x;
            acc[2 * j + 1] += f.y;
        }
    }
    float* o = outAvg + t * 8;
    const float inv = 1.0f / NH;
    *(float4*)o       = make_float4(acc[0] * inv, acc[1] * inv, acc[2] * inv, acc[3] * inv);
    *(float4*)(o + 4) = make_float4(acc[4] * inv, acc[5] * inv, acc[6] * inv, acc[7] * inv);
}

// =====================================================================
extern "C" void kernel_launch(void* const* d_in, const int* in_sizes, int n_in,
                              void* d_out, int out_size)
{
    (void)in_sizes; (void)n_in; (void)out_size;
    const float* q    = (const float*)d_in[0];
    const float* k    = (const float*)d_in[1];
    const float* v    = (const float*)d_in[2];
    const float* Wqkv = (const float*)d_in[3];
    const float* bqkv = (const float*)d_in[4];
    const float* Wo   = (const float*)d_in[5];
    const float* bo   = (const float*)d_in[6];
    float* out    = (float*)d_out;
    float* outAvg = out + (size_t)LQ * BATCH * EMB;

    cudaFuncSetAttribute(k_inproj_cp,  cudaFuncAttributeMaxDynamicSharedMemorySize, PROJ_SMEM);
    cudaFuncSetAttribute(k_outproj_cp, cudaFuncAttributeMaxDynamicSharedMemorySize, PROJ_SMEM);
    cudaFuncSetAttribute(k_attn,       cudaFuncAttributeMaxDynamicSharedMemorySize, ATTN_SMEM);

    __half* inh; __half* wh; __half* woh;
    cudaGetSymbolAddress((void**)&inh, g_inh);
    cudaGetSymbolAddress((void**)&wh,  g_wh);
    cudaGetSymbolAddress((void**)&woh, g_woh);

    const int nIn = MR * EMB / 8;          // 524288
    const int nW  = 3 * EMB * EMB / 8;     // 393216
    const int nWo = EMB * EMB / 8;         // 131072
    k_f2h3<<<dim3((nIn + 255) / 256, 3), 256>>>(q, k, v, inh, nIn);
    k_f2h<<<(nW + 255) / 256, 256>>>(Wqkv, wh, nW);
    k_f2h<<<(nWo + 255) / 256, 256>>>(Wo, woh, nWo);

    k_inproj_cp<<<dim3(EMB / 128, MR / 128, 3), 128, PROJ_SMEM>>>(bqkv);
    k_attn<<<dim3(LQ / 128, BHn), 256, ATTN_SMEM>>>();
    k_avg_h<<<4096, 256>>>(outAvg);
    k_outproj_cp<<<dim3(EMB / 128, MR / 128), 128, PROJ_SMEM>>>(bo, out);
}

// round 14
// speedup vs baseline: 1.1388x; 1.0624x over previous
#include <cuda_runtime.h>
#include <cuda_fp16.h>
#include <math.h>
#include <stdint.h>

// Problem constants
#define LQ    2048
#define BATCH 2
#define EMB   1024
#define NH    16
#define HD    64
#define SK    2048
#define BHn   32
#define MR    4096

// ---------------- scratch (device globals) ----------------
__device__ __half g_inh[3 * MR * EMB];
__device__ __half g_wh[3 * EMB * EMB];
__device__ __half g_woh[EMB * EMB];
__device__ __half g_qh[BHn * LQ * HD];              // pre-scaled 1/16
__device__ __half g_kh[BHn * SK * HD];
__device__ __half g_vth[BHn * HD * SK];
__device__ __half g_attnh[(size_t)BHn * LQ * SK];
__device__ __half g_ctxh[MR * EMB];

// ---------------- helpers ----------------
__device__ __forceinline__ uint32_t f2h2(float a, float b) {
    half2 h = __floats2half2_rn(a, b);
    return *reinterpret_cast<uint32_t*>(&h);
}
__device__ __forceinline__ uint32_t smem_u32(const void* p) {
    return (uint32_t)__cvta_generic_to_shared(p);
}

#define LDSM4(R0,R1,R2,R3,ADDR) \
    asm volatile("ldmatrix.sync.aligned.m8n8.x4.shared.b16 {%0,%1,%2,%3}, [%4];" \
        : "=r"(R0), "=r"(R1), "=r"(R2), "=r"(R3) : "r"(ADDR))

#define MMAH(C,A,B0,B1) \
    asm volatile("mma.sync.aligned.m16n8k16.row.col.f32.f16.f16.f32 " \
        "{%0,%1,%2,%3},{%4,%5,%6,%7},{%8,%9},{%0,%1,%2,%3};" \
        : "+f"((C)[0]), "+f"((C)[1]), "+f"((C)[2]), "+f"((C)[3]) \
        : "r"((A)[0]), "r"((A)[1]), "r"((A)[2]), "r"((A)[3]), "r"(B0), "r"(B1))

#define CPA16(DST, SRC) \
    asm volatile("cp.async.ca.shared.global [%0], [%1], 16;" \
        :: "r"(DST), "l"(SRC) : "memory")
#define CPA_COMMIT() asm volatile("cp.async.commit_group;" ::: "memory")
#define CPA_WAIT0()  asm volatile("cp.async.wait_group 0;" ::: "memory")

#define BARG(ID) asm volatile("bar.sync %0, 128;" :: "r"(ID) : "memory")

// sigmoid(2u): 0.5*tanh(u)+0.5 (Q pre-scaled by extra 0.5)
__device__ __forceinline__ uint32_t sig_h2(float a, float b) {
    uint32_t p = f2h2(a, b);
    asm("tanh.approx.f16x2 %0, %0;" : "+r"(p));
    const half2 H05 = __half2half2(__ushort_as_half(0x3800));
    half2 t = *reinterpret_cast<half2*>(&p);
    t = __hfma2(t, H05, H05);
    return *reinterpret_cast<uint32_t*>(&t);
}

// =====================================================================
// fp32 -> fp16 conversion kernels
// =====================================================================
__global__ __launch_bounds__(256) void k_f2h3(
    const float* __restrict__ s0, const float* __restrict__ s1,
    const float* __restrict__ s2, __half* __restrict__ d, int n8)
{
    const float* s = (blockIdx.y == 0) ? s0 : (blockIdx.y == 1) ? s1 : s2;
    __half* dp = d + (size_t)blockIdx.y * n8 * 8;
    const int i = blockIdx.x * 256 + threadIdx.x;
    if (i < n8) {
        const float4 a = ((const float4*)s)[2 * i];
        const float4 b = ((const float4*)s)[2 * i + 1];
        uint4 o;
        o.x = f2h2(a.x, a.y); o.y = f2h2(a.z, a.w);
        o.z = f2h2(b.x, b.y); o.w = f2h2(b.z, b.w);
        ((uint4*)dp)[i] = o;
    }
}

__global__ __launch_bounds__(256) void k_f2h(const float* __restrict__ s,
                                             __half* __restrict__ d, int n8)
{
    const int i = blockIdx.x * 256 + threadIdx.x;
    if (i < n8) {
        const float4 a = ((const float4*)s)[2 * i];
        const float4 b = ((const float4*)s)[2 * i + 1];
        uint4 o;
        o.x = f2h2(a.x, a.y); o.y = f2h2(a.z, a.w);
        o.z = f2h2(b.x, b.y); o.w = f2h2(b.z, b.w);
        ((uint4*)d)[i] = o;
    }
}

// =====================================================================
// cp.async GEMM core 256x128: 256 thr, 8 warps (4m x 2n), warp 64x64,
// BK=64, 2-stage. smem: A0 @0 (32K) | A1 @32K | B0 @64K (16K) | B1 @80K
// Staging/iter: A 8 CPA16/thr, B 4 CPA16/thr (12 vs 16 per 128-tile pair)
// =====================================================================
__device__ __forceinline__ void gemm_cp256(
    const __half* __restrict__ A, int lda,
    const __half* __restrict__ B, int ldb,
    int K, float (&acc)[4][8][4], char* smem)
{
    const uint32_t sb = smem_u32(smem);
    const int tid = threadIdx.x, lane = tid & 31, warp = tid >> 5;
    const int wm0 = (warp >> 1) * 64, wn0 = (warp & 1) * 64;

    // staging: A row = tid (8 granules); B row = tid>>1, granules (tid&1)*4..+3
    const int sswA = (tid & 7) << 4;
    const int brs = tid >> 1, bg0 = (tid & 1) * 4;
    const int sswB = (brs & 7) << 4;
    const __half* Ap = A + (size_t)tid * lda;
    const __half* Bp = B + (size_t)brs * ldb + bg0 * 8;

    const int arow = wm0 + (lane & 15), agh = lane >> 4, lsw = lane & 7;
    const int brow = wn0 + (lane & 7) + ((lane >> 4) << 3), bgh = (lane >> 3) & 1;
    const uint32_t aB0 = sb + (uint32_t)arow * 128;
    const uint32_t bB0 = sb + 65536u + (uint32_t)brow * 128;

#pragma unroll
    for (int mt = 0; mt < 4; mt++)
#pragma unroll
        for (int nt = 0; nt < 8; nt++)
#pragma unroll
            for (int c = 0; c < 4; c++) acc[mt][nt][c] = 0.0f;

#define P256_ISSUE(t, s) do { \
        const uint32_t _ad = sb + (uint32_t)((s) * 32768) + (uint32_t)tid * 128; \
        const __half* _An = Ap + (t) * 64; \
        _Pragma("unroll") \
        for (int g = 0; g < 8; g++) \
            CPA16(_ad + (uint32_t)((g * 16) ^ sswA), _An + g * 8); \
        const uint32_t _bd = sb + 65536u + (uint32_t)((s) * 16384) + (uint32_t)brs * 128; \
        const __half* _Bn = Bp + (t) * 64; \
        _Pragma("unroll") \
        for (int g = 0; g < 4; g++) \
            CPA16(_bd + (uint32_t)(((bg0 + g) * 16) ^ sswB), _Bn + g * 8); \
        CPA_COMMIT(); \
    } while (0)

    P256_ISSUE(0, 0);

    const int iters = K >> 6;
    for (int it = 0; it < iters; it++) {
        CPA_WAIT0();
        __syncthreads();

        if (it + 1 < iters) P256_ISSUE(it + 1, (it + 1) & 1);

        const uint32_t aB = aB0 + (uint32_t)((it & 1) * 32768);
        const uint32_t bB = bB0 + (uint32_t)((it & 1) * 16384);
#pragma unroll
        for (int ss = 0; ss < 4; ss++) {
            const uint32_t offA = (uint32_t)(((2 * ss + agh) ^ lsw) << 4);
            const uint32_t offB = (uint32_t)(((2 * ss + bgh) ^ lsw) << 4);
            uint32_t af[4][4], bf[4][4];
#pragma unroll
            for (int mt = 0; mt < 4; mt++)
                LDSM4(af[mt][0], af[mt][1], af[mt][2], af[mt][3],
                      aB + (uint32_t)(mt * 2048) + offA);
#pragma unroll
            for (int bt = 0; bt < 4; bt++)
                LDSM4(bf[bt][0], bf[bt][1], bf[bt][2], bf[bt][3],
                      bB + (uint32_t)(bt * 2048) + offB);
#pragma unroll
            for (int mt = 0; mt < 4; mt++)
#pragma unroll
                for (int bt = 0; bt < 4; bt++) {
                    MMAH(acc[mt][2 * bt],     af[mt], bf[bt][0], bf[bt][1]);
                    MMAH(acc[mt][2 * bt + 1], af[mt], bf[bt][2], bf[bt][3]);
                }
        }
    }
#undef P256_ISSUE
}

#define PROJ_SMEM 98304

// =====================================================================
// in-projection: grid (8, 16, 3), 256 thr, CTA tile 256x128.
// =====================================================================
__global__ __launch_bounds__(256, 1) void k_inproj_cp(const float* __restrict__ bias)
{
    extern __shared__ char smem[];
    const int p = blockIdx.z;
    const int m0 = blockIdx.y * 256, n0 = blockIdx.x * 128;
    const __half* A = g_inh + (size_t)p * MR * EMB + (size_t)m0 * EMB;
    const __half* B = g_wh + (size_t)p * EMB * EMB + (size_t)n0 * EMB;
    const float* bp = bias + p * EMB;
    const float scale = (p == 0) ? 0.0625f : 1.0f;

    float acc[4][8][4];
    gemm_cp256(A, EMB, B, EMB, EMB, acc, smem);

    const int lane = threadIdx.x & 31, warp = threadIdx.x >> 5;
    const int wm0 = (warp >> 1) * 64, wn0 = (warp & 1) * 64;

    if (p == 2) {
        // ---- V: transpose via smem (256x130 halves), coalesced stores ----
        __syncthreads();
        __half* ts = (__half*)smem;
        const int STR = 130;
#pragma unroll
        for (int nt = 0; nt < 8; nt++) {
            const int c = wn0 + nt * 8 + 2 * (lane & 3);
            const float b0 = bp[n0 + c], b1 = bp[n0 + c + 1];
#pragma unroll
            for (int mt = 0; mt < 4; mt++) {
                const int r = wm0 + mt * 16 + (lane >> 2);
                *(half2*)&ts[r * STR + c] =
                    __floats2half2_rn(acc[mt][nt][0] + b0, acc[mt][nt][1] + b1);
                *(half2*)&ts[(r + 8) * STR + c] =
                    __floats2half2_rn(acc[mt][nt][2] + b0, acc[mt][nt][3] + b1);
            }
        }
        __syncthreads();
        const int t = threadIdx.x;
        {
            const int col = t & 127;
            const int bb  = t >> 7;
            const int hg  = (n0 >> 6) + (col >> 6);
            const int d   = col & 63;
            __half buf[128];
#pragma unroll
            for (int li = 0; li < 128; li++)
                buf[li] = ts[(2 * li + bb) * STR + col];
            __half* dst = g_vth + ((size_t)(bb * NH + hg) * HD + d) * SK + (m0 >> 1);
#pragma unroll
            for (int g = 0; g < 16; g++)
                *(uint4*)(dst + g * 8) = *(uint4*)(buf + g * 8);
        }
        return;
    }

    // ---- Q / K: stage 256x136 tile in smem, one 128B row per thread/head ----
    __syncthreads();
    __half* ts = (__half*)smem;
    const int STR = 136;
#pragma unroll
    for (int nt = 0; nt < 8; nt++) {
        const int c = wn0 + nt * 8 + 2 * (lane & 3);
        const float b0 = bp[n0 + c], b1 = bp[n0 + c + 1];
#pragma unroll
        for (int mt = 0; mt < 4; mt++) {
            const int r = wm0 + mt * 16 + (lane >> 2);
            *(half2*)&ts[r * STR + c] =
                __floats2half2_rn((acc[mt][nt][0] + b0) * scale,
                                  (acc[mt][nt][1] + b1) * scale);
            *(half2*)&ts[(r + 8) * STR + c] =
                __floats2half2_rn((acc[mt][nt][2] + b0) * scale,
                                  (acc[mt][nt][3] + b1) * scale);
        }
    }
    __syncthreads();
    {
        const int t = threadIdx.x;
        const int l = (m0 + t) >> 1, bb = (m0 + t) & 1;
#pragma unroll
        for (int hh = 0; hh < 2; hh++) {
            const int hg = (n0 >> 6) + hh;
            const int bh = bb * NH + hg;
            uint4 buf[8];
#pragma unroll
            for (int g = 0; g < 8; g++)
                buf[g] = *(uint4*)&ts[t * STR + hh * 64 + g * 8];
            __half* dst = (p == 0 ? g_qh : g_kh) + ((size_t)bh * LQ + l) * HD;
#pragma unroll
            for (int g = 0; g < 8; g++)
                *(uint4*)(dst + g * 8) = buf[g];
        }
    }
}

// =====================================================================
// out-projection: grid (8, 16), 256 thr, CTA tile 256x128.
// =====================================================================
__global__ __launch_bounds__(256, 1) void k_outproj_cp(
    const float* __restrict__ bo, float* __restrict__ out)
{
    extern __shared__ char smem[];
    const int m0 = blockIdx.y * 256, n0 = blockIdx.x * 128;

    float acc[4][8][4];
    gemm_cp256(g_ctxh + (size_t)m0 * EMB, EMB, g_woh + (size_t)n0 * EMB, EMB, EMB, acc, smem);

    const int lane = threadIdx.x & 31, warp = threadIdx.x >> 5;
    const int wm0 = (warp >> 1) * 64, wn0 = (warp & 1) * 64;

#pragma unroll
    for (int nt = 0; nt < 8; nt++) {
        const int c = n0 + wn0 + nt * 8 + 2 * (lane & 3);
        const float b0 = bo[c], b1 = bo[c + 1];
#pragma unroll
        for (int mt = 0; mt < 4; mt++) {
            const int r = m0 + wm0 + mt * 16 + (lane >> 2);
            *(float2*)&out[(size_t)r * EMB + c] =
                make_float2(acc[mt][nt][0] + b0, acc[mt][nt][1] + b1);
            *(float2*)&out[(size_t)(r + 8) * EMB + c] =
                make_float2(acc[mt][nt][2] + b0, acc[mt][nt][3] + b1);
        }
    }
}

// =====================================================================
// FUSED attention (R12 winner, unchanged): CTA = (128 l-rows, bh),
// 256 thr = 2 groups x 4 warps, warp 32m x 64s, register-direct P,
// P@ones denominators, named barriers.
// =====================================================================
#define AT_Q     1024
#define AT_G0    17408
#define AT_GSZ   32768
#define AT_VOFF  16384
#define ATTN_SMEM (AT_G0 + 2 * AT_GSZ)   // 82944

__global__ __launch_bounds__(256, 1) void k_attn()
{
    extern __shared__ char smem[];
    const uint32_t sb = smem_u32(smem);

    const int bh = blockIdx.y;
    const int l0 = blockIdx.x * 128;
    const int b = bh >> 4, h = bh & 15;
    const int tid = threadIdx.x, lane = tid & 31, warp = tid >> 5;
    const int wg = warp >> 2;
    const int wl = warp & 3;
    const int wm = wl * 32;
    const uint32_t gb = AT_G0 + (uint32_t)wg * AT_GSZ;
    const int lt = tid & 127;
    const int barid = 1 + wg;
    const uint32_t ONES = 0x3C003C00u;

    // ---- Q staging ----
    {
        const int qr = tid >> 1, qg = (tid & 1) * 4;
        const int qsw = (qr & 7) << 4;
        const __half* qs = g_qh + ((size_t)bh * LQ + l0 + qr) * HD + qg * 8;
        const uint32_t qd = sb + AT_Q + (uint32_t)qr * 128;
#pragma unroll
        for (int gi = 0; gi < 4; gi++)
            CPA16(qd + (uint32_t)((((qg + gi) * 16)) ^ qsw), qs + gi * 8);
    }
    // K/V staging (per group)
    const int kvrow = lt >> 1, cg0 = (lt & 1) * 4;
    const int ksw = (kvrow & 7) << 4;
    const __half* kp = g_kh  + ((size_t)bh * SK + wg * 64 + kvrow) * HD + (lt & 1) * 32;
    const __half* vp = g_vth + ((size_t)bh * HD + kvrow) * SK + wg * 64 + (lt & 1) * 32;
    {
        const uint32_t kd = sb + gb + (uint32_t)kvrow * 128;
        const uint32_t vd = kd + AT_VOFF;
#pragma unroll
        for (int gi = 0; gi < 4; gi++) {
            CPA16(kd + (uint32_t)(((cg0 + gi) * 16) ^ ksw), kp + gi * 8);
            CPA16(vd + (uint32_t)(((cg0 + gi) * 16) ^ ksw), vp + gi * 8);
        }
        CPA_COMMIT();
    }

    const int aRow = wm + (lane & 15), agh = lane >> 4, lsw = lane & 7;
    const int bRow = (lane & 7) + ((lane >> 4) << 3), bgh = (lane >> 3) & 1;
    const uint32_t aQ  = sb + AT_Q + (uint32_t)aRow * 128;
    const uint32_t bK0 = sb + gb + (uint32_t)bRow * 128;
    const uint32_t bV0 = bK0 + AT_VOFF;

    float acc_pv[2][8][4], acc_den[2][4];
#pragma unroll
    for (int mt = 0; mt < 2; mt++) {
#pragma unroll
        for (int c = 0; c < 4; c++) acc_den[mt][c] = 0.0f;
#pragma unroll
        for (int nt = 0; nt < 8; nt++)
#pragma unroll
            for (int c = 0; c < 4; c++) acc_pv[mt][nt][c] = 0.0f;
    }

    const int r0b = wm + (lane >> 2);
    const int c0b = 2 * (lane & 3);

    for (int it = 0; it < 16; it++) {
        CPA_WAIT0();
        if (it == 0) __syncthreads();
        else BARG(barid);

        if (it < 15) {
            kp += (size_t)128 * HD;
            vp += 128;
            const uint32_t kd = sb + gb + (uint32_t)(((it + 1) & 1) * 8192)
                              + (uint32_t)kvrow * 128;
            const uint32_t vd = kd + AT_VOFF;
#pragma unroll
            for (int gi = 0; gi < 4; gi++) {
                CPA16(kd + (uint32_t)(((cg0 + gi) * 16) ^ ksw), kp + gi * 8);
                CPA16(vd + (uint32_t)(((cg0 + gi) * 16) ^ ksw), vp + gi * 8);
            }
            CPA_COMMIT();
        }

        const uint32_t bufo = (uint32_t)((it & 1) * 8192);
        const uint32_t bK = bK0 + bufo, bV = bV0 + bufo;

        // ---- QK^T ----
        float acc_qk[2][8][4];
#pragma unroll
        for (int mt = 0; mt < 2; mt++)
#pragma unroll
            for (int nt = 0; nt < 8; nt++)
#pragma unroll
                for (int c = 0; c < 4; c++) acc_qk[mt][nt][c] = 0.0f;

#pragma unroll
        for (int ss = 0; ss < 4; ss++) {
            const uint32_t offA = (uint32_t)(((2 * ss + agh) ^ lsw) << 4);
            const uint32_t offB = (uint32_t)(((2 * ss + bgh) ^ lsw) << 4);
            uint32_t af[2][4], bf[4][4];
#pragma unroll
            for (int mt = 0; mt < 2; mt++)
                LDSM4(af[mt][0], af[mt][1], af[mt][2], af[mt][3],
                      aQ + (uint32_t)(mt * 2048) + offA);
#pragma unroll
            for (int bt = 0; bt < 4; bt++)
                LDSM4(bf[bt][0], bf[bt][1], bf[bt][2], bf[bt][3],
                      bK + (uint32_t)(bt * 2048) + offB);
#pragma unroll
            for (int mt = 0; mt < 2; mt++)
#pragma unroll
                for (int bt = 0; bt < 4; bt++) {
                    MMAH(acc_qk[mt][2 * bt],     af[mt], bf[bt][0], bf[bt][1]);
                    MMAH(acc_qk[mt][2 * bt + 1], af[mt], bf[bt][2], bf[bt][3]);
                }
        }

        // ---- sigmoid: register-direct pack + attn STG ----
        const int s0 = (2 * it + wg) * 64;
        uint32_t pa[2][4][4];
#pragma unroll
        for (int mt = 0; mt < 2; mt++) {
            const int r0 = r0b + mt * 16;
            __half* ar0 = g_attnh + ((size_t)bh * LQ + l0 + r0) * SK + s0 + c0b;
            __half* ar1 = ar0 + 8 * SK;
#pragma unroll
            for (int nt = 0; nt < 8; nt++) {
                const uint32_t p01 = sig_h2(acc_qk[mt][nt][0], acc_qk[mt][nt][1]);
                const uint32_t p23 = sig_h2(acc_qk[mt][nt][2], acc_qk[mt][nt][3]);
                *(uint32_t*)(ar0 + nt * 8) = p01;
                *(uint32_t*)(ar1 + nt * 8) = p23;
                pa[mt][nt >> 1][(nt & 1) ? 2 : 0] = p01;
                pa[mt][nt >> 1][(nt & 1) ? 3 : 1] = p23;
            }
        }

        // ---- P @ V^T (A from registers) + P @ ones ----
#pragma unroll
        for (int ss = 0; ss < 4; ss++) {
            const uint32_t offB = (uint32_t)(((2 * ss + bgh) ^ lsw) << 4);
            uint32_t bf[4][4];
#pragma unroll
            for (int bt = 0; bt < 4; bt++)
                LDSM4(bf[bt][0], bf[bt][1], bf[bt][2], bf[bt][3],
                      bV + (uint32_t)(bt * 2048) + offB);
#pragma unroll
            for (int mt = 0; mt < 2; mt++) {
#pragma unroll
                for (int bt = 0; bt < 4; bt++) {
                    MMAH(acc_pv[mt][2 * bt],     pa[mt][ss], bf[bt][0], bf[bt][1]);
                    MMAH(acc_pv[mt][2 * bt + 1], pa[mt][ss], bf[bt][2], bf[bt][3]);
                }
                MMAH(acc_den[mt], pa[mt][ss], ONES, ONES);
            }
        }
    }

    // ---- cross-group merge ----
    __syncthreads();
    float* scr = (float*)(smem + AT_Q);
    if (tid >= 128) {
        const int t = tid - 128;
#pragma unroll
        for (int mt = 0; mt < 2; mt++) {
#pragma unroll
            for (int nt = 0; nt < 8; nt++)
#pragma unroll
                for (int c = 0; c < 4; c++)
                    scr[t * 69 + (mt * 8 + nt) * 4 + c] = acc_pv[mt][nt][c];
            scr[t * 69 + 64 + mt * 2]     = acc_den[mt][0];
            scr[t * 69 + 64 + mt * 2 + 1] = acc_den[mt][2];
        }
    }
    __syncthreads();
    if (tid < 128) {
#pragma unroll
        for (int mt = 0; mt < 2; mt++) {
            const int rl = wm + mt * 16 + (lane >> 2);
            const float den0 = acc_den[mt][0] + scr[tid * 69 + 64 + mt * 2];
            const float den1 = acc_den[mt][2] + scr[tid * 69 + 64 + mt * 2 + 1];
            const float inv0 = __fdividef(1.0f, den0 + 1e-4f);
            const float inv1 = __fdividef(1.0f, den1 + 1e-4f);
            const int l = l0 + rl;
#pragma unroll
            for (int nt = 0; nt < 8; nt++) {
                const int c = nt * 8 + 2 * (lane & 3);
                const int si = tid * 69 + (mt * 8 + nt) * 4;
                const float o0 = (acc_pv[mt][nt][0] + scr[si + 0]) * inv0;
                const float o1 = (acc_pv[mt][nt][1] + scr[si + 1]) * inv0;
                const float o2 = (acc_pv[mt][nt][2] + scr[si + 2]) * inv1;
                const float o3 = (acc_pv[mt][nt][3] + scr[si + 3]) * inv1;
                *(half2*)&g_ctxh[(size_t)(l * BATCH + b) * EMB + h * HD + c] =
                    __floats2half2_rn(o0, o1);
                *(half2*)&g_ctxh[(size_t)((l + 8) * BATCH + b) * EMB + h * HD + c] =
                    __floats2half2_rn(o2, o3);
            }
        }
    }
}

// =====================================================================
// avg_weights from fp16 attn: grid 4096, 256 thr
// =====================================================================
__global__ __launch_bounds__(256) void k_avg_h(float* __restrict__ outAvg)
{
    const size_t t = (size_t)blockIdx.x * 256 + threadIdx.x;
    const int s8 = (int)(t & (SK / 8 - 1));
    const int l  = (int)((t >> 8) & (LQ - 1));
    const int b  = (int)(t >> 19);
    float acc[8] = {0, 0, 0, 0, 0, 0, 0, 0};
#pragma unroll
    for (int h = 0; h < NH; h++) {
        const uint4 u = *(const uint4*)&g_attnh[((size_t)(b * NH + h) * LQ + l) * SK + s8 * 8];
        const half2* p = (const half2*)&u;
#pragma unroll
        for (int j = 0; j < 4; j++) {
            const float2 f = __half22float2(p[j]);
            acc[2 * j]     += f.x;
            acc[2 * j + 1] += f.y;
        }
    }
    float* o = outAvg + t * 8;
    const float inv = 1.0f / NH;
    *(float4*)o       = make_float4(acc[0] * inv, acc[1] * inv, acc[2] * inv, acc[3] * inv);
    *(float4*)(o + 4) = make_float4(acc[4] * inv, acc[5] * inv, acc[6] * inv, acc[7] * inv);
}

// =====================================================================
extern "C" void kernel_launch(void* const* d_in, const int* in_sizes, int n_in,
                              void* d_out, int out_size)
{
    (void)in_sizes; (void)n_in; (void)out_size;
    const float* q    = (const float*)d_in[0];
    const float* k    = (const float*)d_in[1];
    const float* v    = (const float*)d_in[2];
    const float* Wqkv = (const float*)d_in[3];
    const float* bqkv = (const float*)d_in[4];
    const float* Wo   = (const float*)d_in[5];
    const float* bo   = (const float*)d_in[6];
    float* out    = (float*)d_out;
    float* outAvg = out + (size_t)LQ * BATCH * EMB;

    cudaFuncSetAttribute(k_inproj_cp,  cudaFuncAttributeMaxDynamicSharedMemorySize, PROJ_SMEM);
    cudaFuncSetAttribute(k_outproj_cp, cudaFuncAttributeMaxDynamicSharedMemorySize, PROJ_SMEM);
    cudaFuncSetAttribute(k_attn,       cudaFuncAttributeMaxDynamicSharedMemorySize, ATTN_SMEM);

    __half* inh; __half* wh; __half* woh;
    cudaGetSymbolAddress((void**)&inh, g_inh);
    cudaGetSymbolAddress((void**)&wh,  g_wh);
    cudaGetSymbolAddress((void**)&woh, g_woh);

    const int nIn = MR * EMB / 8;          // 524288
    const int nW  = 3 * EMB * EMB / 8;     // 393216
    const int nWo = EMB * EMB / 8;         // 131072
    k_f2h3<<<dim3((nIn + 255) / 256, 3), 256>>>(q, k, v, inh, nIn);
    k_f2h<<<(nW + 255) / 256, 256>>>(Wqkv, wh, nW);
    k_f2h<<<(nWo + 255) / 256, 256>>>(Wo, woh, nWo);

    k_inproj_cp<<<dim3(EMB / 128, MR / 256, 3), 256, PROJ_SMEM>>>(bqkv);
    k_attn<<<dim3(LQ / 128, BHn), 256, ATTN_SMEM>>>();
    k_avg_h<<<4096, 256>>>(outAvg);
    k_outproj_cp<<<dim3(EMB / 128, MR / 256), 256, PROJ_SMEM>>>(bo, out);
}

// round 15
// speedup vs baseline: 1.1759x; 1.0326x over previous
#include <cuda_runtime.h>
#include <cuda_fp16.h>
#include <math.h>
#include <stdint.h>

// Problem constants
#define LQ    2048
#define BATCH 2
#define EMB   1024
#define NH    16
#define HD    64
#define SK    2048
#define BHn   32
#define MR    4096

// ---------------- scratch (device globals) ----------------
__device__ __half g_inh[3 * MR * EMB];
__device__ __half g_wh[3 * EMB * EMB];
__device__ __half g_woh[EMB * EMB];
__device__ __half g_qh[BHn * LQ * HD];              // pre-scaled 1/16
__device__ __half g_kh[BHn * SK * HD];
__device__ __half g_vth[BHn * HD * SK];
__device__ __half g_attnh[(size_t)BHn * LQ * SK];
__device__ __half g_ctxh[MR * EMB];

// ---------------- helpers ----------------
__device__ __forceinline__ uint32_t f2h2(float a, float b) {
    half2 h = __floats2half2_rn(a, b);
    return *reinterpret_cast<uint32_t*>(&h);
}
__device__ __forceinline__ uint32_t smem_u32(const void* p) {
    return (uint32_t)__cvta_generic_to_shared(p);
}

#define LDSM4(R0,R1,R2,R3,ADDR) \
    asm volatile("ldmatrix.sync.aligned.m8n8.x4.shared.b16 {%0,%1,%2,%3}, [%4];" \
        : "=r"(R0), "=r"(R1), "=r"(R2), "=r"(R3) : "r"(ADDR))

#define MMAH(C,A,B0,B1) \
    asm volatile("mma.sync.aligned.m16n8k16.row.col.f32.f16.f16.f32 " \
        "{%0,%1,%2,%3},{%4,%5,%6,%7},{%8,%9},{%0,%1,%2,%3};" \
        : "+f"((C)[0]), "+f"((C)[1]), "+f"((C)[2]), "+f"((C)[3]) \
        : "r"((A)[0]), "r"((A)[1]), "r"((A)[2]), "r"((A)[3]), "r"(B0), "r"(B1))

#define CPA16(DST, SRC) \
    asm volatile("cp.async.ca.shared.global [%0], [%1], 16;" \
        :: "r"(DST), "l"(SRC) : "memory")
#define CPA_COMMIT() asm volatile("cp.async.commit_group;" ::: "memory")
#define CPA_WAIT0()  asm volatile("cp.async.wait_group 0;" ::: "memory")

#define BARG(ID) asm volatile("bar.sync %0, 128;" :: "r"(ID) : "memory")

// sigmoid(2u): 0.5*tanh(u)+0.5 (Q pre-scaled by extra 0.5)
__device__ __forceinline__ uint32_t sig_h2(float a, float b) {
    uint32_t p = f2h2(a, b);
    asm("tanh.approx.f16x2 %0, %0;" : "+r"(p));
    const half2 H05 = __half2half2(__ushort_as_half(0x3800));
    half2 t = *reinterpret_cast<half2*>(&p);
    t = __hfma2(t, H05, H05);
    return *reinterpret_cast<uint32_t*>(&t);
}

// =====================================================================
// fp32 -> fp16 conversion kernels
// =====================================================================
__global__ __launch_bounds__(256) void k_f2h3(
    const float* __restrict__ s0, const float* __restrict__ s1,
    const float* __restrict__ s2, __half* __restrict__ d, int n8)
{
    const float* s = (blockIdx.y == 0) ? s0 : (blockIdx.y == 1) ? s1 : s2;
    __half* dp = d + (size_t)blockIdx.y * n8 * 8;
    const int i = blockIdx.x * 256 + threadIdx.x;
    if (i < n8) {
        const float4 a = ((const float4*)s)[2 * i];
        const float4 b = ((const float4*)s)[2 * i + 1];
        uint4 o;
        o.x = f2h2(a.x, a.y); o.y = f2h2(a.z, a.w);
        o.z = f2h2(b.x, b.y); o.w = f2h2(b.z, b.w);
        ((uint4*)dp)[i] = o;
    }
}

__global__ __launch_bounds__(256) void k_f2h(const float* __restrict__ s,
                                             __half* __restrict__ d, int n8)
{
    const int i = blockIdx.x * 256 + threadIdx.x;
    if (i < n8) {
        const float4 a = ((const float4*)s)[2 * i];
        const float4 b = ((const float4*)s)[2 * i + 1];
        uint4 o;
        o.x = f2h2(a.x, a.y); o.y = f2h2(a.z, a.w);
        o.z = f2h2(b.x, b.y); o.w = f2h2(b.z, b.w);
        ((uint4*)d)[i] = o;
    }
}

// =====================================================================
// cp.async GEMM core 256x128: 256 thr, 8 warps (4m x 2n), warp 64x64,
// BK=64, 2-stage. smem: A0 @0 (32K) | A1 @32K | B0 @64K (16K) | B1 @80K
// =====================================================================
__device__ __forceinline__ void gemm_cp256(
    const __half* __restrict__ A, int lda,
    const __half* __restrict__ B, int ldb,
    int K, float (&acc)[4][8][4], char* smem)
{
    const uint32_t sb = smem_u32(smem);
    const int tid = threadIdx.x, lane = tid & 31, warp = tid >> 5;
    const int wm0 = (warp >> 1) * 64, wn0 = (warp & 1) * 64;

    const int sswA = (tid & 7) << 4;
    const int brs = tid >> 1, bg0 = (tid & 1) * 4;
    const int sswB = (brs & 7) << 4;
    const __half* Ap = A + (size_t)tid * lda;
    const __half* Bp = B + (size_t)brs * ldb + bg0 * 8;

    const int arow = wm0 + (lane & 15), agh = lane >> 4, lsw = lane & 7;
    const int brow = wn0 + (lane & 7) + ((lane >> 4) << 3), bgh = (lane >> 3) & 1;
    const uint32_t aB0 = sb + (uint32_t)arow * 128;
    const uint32_t bB0 = sb + 65536u + (uint32_t)brow * 128;

#pragma unroll
    for (int mt = 0; mt < 4; mt++)
#pragma unroll
        for (int nt = 0; nt < 8; nt++)
#pragma unroll
            for (int c = 0; c < 4; c++) acc[mt][nt][c] = 0.0f;

#define P256_ISSUE(t, s) do { \
        const uint32_t _ad = sb + (uint32_t)((s) * 32768) + (uint32_t)tid * 128; \
        const __half* _An = Ap + (t) * 64; \
        _Pragma("unroll") \
        for (int g = 0; g < 8; g++) \
            CPA16(_ad + (uint32_t)((g * 16) ^ sswA), _An + g * 8); \
        const uint32_t _bd = sb + 65536u + (uint32_t)((s) * 16384) + (uint32_t)brs * 128; \
        const __half* _Bn = Bp + (t) * 64; \
        _Pragma("unroll") \
        for (int g = 0; g < 4; g++) \
            CPA16(_bd + (uint32_t)(((bg0 + g) * 16) ^ sswB), _Bn + g * 8); \
        CPA_COMMIT(); \
    } while (0)

    P256_ISSUE(0, 0);

    const int iters = K >> 6;
    for (int it = 0; it < iters; it++) {
        CPA_WAIT0();
        __syncthreads();

        if (it + 1 < iters) P256_ISSUE(it + 1, (it + 1) & 1);

        const uint32_t aB = aB0 + (uint32_t)((it & 1) * 32768);
        const uint32_t bB = bB0 + (uint32_t)((it & 1) * 16384);
#pragma unroll
        for (int ss = 0; ss < 4; ss++) {
            const uint32_t offA = (uint32_t)(((2 * ss + agh) ^ lsw) << 4);
            const uint32_t offB = (uint32_t)(((2 * ss + bgh) ^ lsw) << 4);
            uint32_t af[4][4], bf[4][4];
#pragma unroll
            for (int mt = 0; mt < 4; mt++)
                LDSM4(af[mt][0], af[mt][1], af[mt][2], af[mt][3],
                      aB + (uint32_t)(mt * 2048) + offA);
#pragma unroll
            for (int bt = 0; bt < 4; bt++)
                LDSM4(bf[bt][0], bf[bt][1], bf[bt][2], bf[bt][3],
                      bB + (uint32_t)(bt * 2048) + offB);
#pragma unroll
            for (int mt = 0; mt < 4; mt++)
#pragma unroll
                for (int bt = 0; bt < 4; bt++) {
                    MMAH(acc[mt][2 * bt],     af[mt], bf[bt][0], bf[bt][1]);
                    MMAH(acc[mt][2 * bt + 1], af[mt], bf[bt][2], bf[bt][3]);
                }
        }
    }
#undef P256_ISSUE
}

#define PROJ_SMEM 98304

// =====================================================================
// in-projection: grid (8, 16, 3), 256 thr, CTA tile 256x128.
// =====================================================================
__global__ __launch_bounds__(256, 1) void k_inproj_cp(const float* __restrict__ bias)
{
    extern __shared__ char smem[];
    const int p = blockIdx.z;
    const int m0 = blockIdx.y * 256, n0 = blockIdx.x * 128;
    const __half* A = g_inh + (size_t)p * MR * EMB + (size_t)m0 * EMB;
    const __half* B = g_wh + (size_t)p * EMB * EMB + (size_t)n0 * EMB;
    const float* bp = bias + p * EMB;
    const float scale = (p == 0) ? 0.0625f : 1.0f;

    float acc[4][8][4];
    gemm_cp256(A, EMB, B, EMB, EMB, acc, smem);

    const int lane = threadIdx.x & 31, warp = threadIdx.x >> 5;
    const int wm0 = (warp >> 1) * 64, wn0 = (warp & 1) * 64;

    if (p == 2) {
        __syncthreads();
        __half* ts = (__half*)smem;
        const int STR = 130;
#pragma unroll
        for (int nt = 0; nt < 8; nt++) {
            const int c = wn0 + nt * 8 + 2 * (lane & 3);
            const float b0 = bp[n0 + c], b1 = bp[n0 + c + 1];
#pragma unroll
            for (int mt = 0; mt < 4; mt++) {
                const int r = wm0 + mt * 16 + (lane >> 2);
                *(half2*)&ts[r * STR + c] =
                    __floats2half2_rn(acc[mt][nt][0] + b0, acc[mt][nt][1] + b1);
                *(half2*)&ts[(r + 8) * STR + c] =
                    __floats2half2_rn(acc[mt][nt][2] + b0, acc[mt][nt][3] + b1);
            }
        }
        __syncthreads();
        const int t = threadIdx.x;
        {
            const int col = t & 127;
            const int bb  = t >> 7;
            const int hg  = (n0 >> 6) + (col >> 6);
            const int d   = col & 63;
            __half buf[128];
#pragma unroll
            for (int li = 0; li < 128; li++)
                buf[li] = ts[(2 * li + bb) * STR + col];
            __half* dst = g_vth + ((size_t)(bb * NH + hg) * HD + d) * SK + (m0 >> 1);
#pragma unroll
            for (int g = 0; g < 16; g++)
                *(uint4*)(dst + g * 8) = *(uint4*)(buf + g * 8);
        }
        return;
    }

    __syncthreads();
    __half* ts = (__half*)smem;
    const int STR = 136;
#pragma unroll
    for (int nt = 0; nt < 8; nt++) {
        const int c = wn0 + nt * 8 + 2 * (lane & 3);
        const float b0 = bp[n0 + c], b1 = bp[n0 + c + 1];
#pragma unroll
        for (int mt = 0; mt < 4; mt++) {
            const int r = wm0 + mt * 16 + (lane >> 2);
            *(half2*)&ts[r * STR + c] =
                __floats2half2_rn((acc[mt][nt][0] + b0) * scale,
                                  (acc[mt][nt][1] + b1) * scale);
            *(half2*)&ts[(r + 8) * STR + c] =
                __floats2half2_rn((acc[mt][nt][2] + b0) * scale,
                                  (acc[mt][nt][3] + b1) * scale);
        }
    }
    __syncthreads();
    {
        const int t = threadIdx.x;
        const int l = (m0 + t) >> 1, bb = (m0 + t) & 1;
#pragma unroll
        for (int hh = 0; hh < 2; hh++) {
            const int hg = (n0 >> 6) + hh;
            const int bh = bb * NH + hg;
            uint4 buf[8];
#pragma unroll
            for (int g = 0; g < 8; g++)
                buf[g] = *(uint4*)&ts[t * STR + hh * 64 + g * 8];
            __half* dst = (p == 0 ? g_qh : g_kh) + ((size_t)bh * LQ + l) * HD;
#pragma unroll
            for (int g = 0; g < 8; g++)
                *(uint4*)(dst + g * 8) = buf[g];
        }
    }
}

// =====================================================================
// out-projection: grid (8, 16), 256 thr, CTA tile 256x128.
// =====================================================================
__global__ __launch_bounds__(256, 1) void k_outproj_cp(
    const float* __restrict__ bo, float* __restrict__ out)
{
    extern __shared__ char smem[];
    const int m0 = blockIdx.y * 256, n0 = blockIdx.x * 128;

    float acc[4][8][4];
    gemm_cp256(g_ctxh + (size_t)m0 * EMB, EMB, g_woh + (size_t)n0 * EMB, EMB, EMB, acc, smem);

    const int lane = threadIdx.x & 31, warp = threadIdx.x >> 5;
    const int wm0 = (warp >> 1) * 64, wn0 = (warp & 1) * 64;

#pragma unroll
    for (int nt = 0; nt < 8; nt++) {
        const int c = n0 + wn0 + nt * 8 + 2 * (lane & 3);
        const float b0 = bo[c], b1 = bo[c + 1];
#pragma unroll
        for (int mt = 0; mt < 4; mt++) {
            const int r = m0 + wm0 + mt * 16 + (lane >> 2);
            *(float2*)&out[(size_t)r * EMB + c] =
                make_float2(acc[mt][nt][0] + b0, acc[mt][nt][1] + b1);
            *(float2*)&out[(size_t)(r + 8) * EMB + c] =
                make_float2(acc[mt][nt][2] + b0, acc[mt][nt][3] + b1);
        }
    }
}

// =====================================================================
// FUSED attention (R12 winner): CTA = (128 l-rows, bh), 256 thr =
// 2 groups x 4 warps, warp 32m x 64s, register-direct P, P@ones denoms.
// =====================================================================
#define AT_Q     1024
#define AT_G0    17408
#define AT_GSZ   32768
#define AT_VOFF  16384
#define ATTN_SMEM (AT_G0 + 2 * AT_GSZ)   // 82944

__global__ __launch_bounds__(256, 1) void k_attn()
{
    extern __shared__ char smem[];
    const uint32_t sb = smem_u32(smem);

    const int bh = blockIdx.y;
    const int l0 = blockIdx.x * 128;
    const int b = bh >> 4, h = bh & 15;
    const int tid = threadIdx.x, lane = tid & 31, warp = tid >> 5;
    const int wg = warp >> 2;
    const int wl = warp & 3;
    const int wm = wl * 32;
    const uint32_t gb = AT_G0 + (uint32_t)wg * AT_GSZ;
    const int lt = tid & 127;
    const int barid = 1 + wg;
    const uint32_t ONES = 0x3C003C00u;

    {
        const int qr = tid >> 1, qg = (tid & 1) * 4;
        const int qsw = (qr & 7) << 4;
        const __half* qs = g_qh + ((size_t)bh * LQ + l0 + qr) * HD + qg * 8;
        const uint32_t qd = sb + AT_Q + (uint32_t)qr * 128;
#pragma unroll
        for (int gi = 0; gi < 4; gi++)
            CPA16(qd + (uint32_t)((((qg + gi) * 16)) ^ qsw), qs + gi * 8);
    }
    const int kvrow = lt >> 1, cg0 = (lt & 1) * 4;
    const int ksw = (kvrow & 7) << 4;
    const __half* kp = g_kh  + ((size_t)bh * SK + wg * 64 + kvrow) * HD + (lt & 1) * 32;
    const __half* vp = g_vth + ((size_t)bh * HD + kvrow) * SK + wg * 64 + (lt & 1) * 32;
    {
        const uint32_t kd = sb + gb + (uint32_t)kvrow * 128;
        const uint32_t vd = kd + AT_VOFF;
#pragma unroll
        for (int gi = 0; gi < 4; gi++) {
            CPA16(kd + (uint32_t)(((cg0 + gi) * 16) ^ ksw), kp + gi * 8);
            CPA16(vd + (uint32_t)(((cg0 + gi) * 16) ^ ksw), vp + gi * 8);
        }
        CPA_COMMIT();
    }

    const int aRow = wm + (lane & 15), agh = lane >> 4, lsw = lane & 7;
    const int bRow = (lane & 7) + ((lane >> 4) << 3), bgh = (lane >> 3) & 1;
    const uint32_t aQ  = sb + AT_Q + (uint32_t)aRow * 128;
    const uint32_t bK0 = sb + gb + (uint32_t)bRow * 128;
    const uint32_t bV0 = bK0 + AT_VOFF;

    float acc_pv[2][8][4], acc_den[2][4];
#pragma unroll
    for (int mt = 0; mt < 2; mt++) {
#pragma unroll
        for (int c = 0; c < 4; c++) acc_den[mt][c] = 0.0f;
#pragma unroll
        for (int nt = 0; nt < 8; nt++)
#pragma unroll
            for (int c = 0; c < 4; c++) acc_pv[mt][nt][c] = 0.0f;
    }

    const int r0b = wm + (lane >> 2);
    const int c0b = 2 * (lane & 3);

    for (int it = 0; it < 16; it++) {
        CPA_WAIT0();
        if (it == 0) __syncthreads();
        else BARG(barid);

        if (it < 15) {
            kp += (size_t)128 * HD;
            vp += 128;
            const uint32_t kd = sb + gb + (uint32_t)(((it + 1) & 1) * 8192)
                              + (uint32_t)kvrow * 128;
            const uint32_t vd = kd + AT_VOFF;
#pragma unroll
            for (int gi = 0; gi < 4; gi++) {
                CPA16(kd + (uint32_t)(((cg0 + gi) * 16) ^ ksw), kp + gi * 8);
                CPA16(vd + (uint32_t)(((cg0 + gi) * 16) ^ ksw), vp + gi * 8);
            }
            CPA_COMMIT();
        }

        const uint32_t bufo = (uint32_t)((it & 1) * 8192);
        const uint32_t bK = bK0 + bufo, bV = bV0 + bufo;

        float acc_qk[2][8][4];
#pragma unroll
        for (int mt = 0; mt < 2; mt++)
#pragma unroll
            for (int nt = 0; nt < 8; nt++)
#pragma unroll
                for (int c = 0; c < 4; c++) acc_qk[mt][nt][c] = 0.0f;

#pragma unroll
        for (int ss = 0; ss < 4; ss++) {
            const uint32_t offA = (uint32_t)(((2 * ss + agh) ^ lsw) << 4);
            const uint32_t offB = (uint32_t)(((2 * ss + bgh) ^ lsw) << 4);
            uint32_t af[2][4], bf[4][4];
#pragma unroll
            for (int mt = 0; mt < 2; mt++)
                LDSM4(af[mt][0], af[mt][1], af[mt][2], af[mt][3],
                      aQ + (uint32_t)(mt * 2048) + offA);
#pragma unroll
            for (int bt = 0; bt < 4; bt++)
                LDSM4(bf[bt][0], bf[bt][1], bf[bt][2], bf[bt][3],
                      bK + (uint32_t)(bt * 2048) + offB);
#pragma unroll
            for (int mt = 0; mt < 2; mt++)
#pragma unroll
                for (int bt = 0; bt < 4; bt++) {
                    MMAH(acc_qk[mt][2 * bt],     af[mt], bf[bt][0], bf[bt][1]);
                    MMAH(acc_qk[mt][2 * bt + 1], af[mt], bf[bt][2], bf[bt][3]);
                }
        }

        const int s0 = (2 * it + wg) * 64;
        uint32_t pa[2][4][4];
#pragma unroll
        for (int mt = 0; mt < 2; mt++) {
            const int r0 = r0b + mt * 16;
            __half* ar0 = g_attnh + ((size_t)bh * LQ + l0 + r0) * SK + s0 + c0b;
            __half* ar1 = ar0 + 8 * SK;
#pragma unroll
            for (int nt = 0; nt < 8; nt++) {
                const uint32_t p01 = sig_h2(acc_qk[mt][nt][0], acc_qk[mt][nt][1]);
                const uint32_t p23 = sig_h2(acc_qk[mt][nt][2], acc_qk[mt][nt][3]);
                *(uint32_t*)(ar0 + nt * 8) = p01;
                *(uint32_t*)(ar1 + nt * 8) = p23;
                pa[mt][nt >> 1][(nt & 1) ? 2 : 0] = p01;
                pa[mt][nt >> 1][(nt & 1) ? 3 : 1] = p23;
            }
        }

#pragma unroll
        for (int ss = 0; ss < 4; ss++) {
            const uint32_t offB = (uint32_t)(((2 * ss + bgh) ^ lsw) << 4);
            uint32_t bf[4][4];
#pragma unroll
            for (int bt = 0; bt < 4; bt++)
                LDSM4(bf[bt][0], bf[bt][1], bf[bt][2], bf[bt][3],
                      bV + (uint32_t)(bt * 2048) + offB);
#pragma unroll
            for (int mt = 0; mt < 2; mt++) {
#pragma unroll
                for (int bt = 0; bt < 4; bt++) {
                    MMAH(acc_pv[mt][2 * bt],     pa[mt][ss], bf[bt][0], bf[bt][1]);
                    MMAH(acc_pv[mt][2 * bt + 1], pa[mt][ss], bf[bt][2], bf[bt][3]);
                }
                MMAH(acc_den[mt], pa[mt][ss], ONES, ONES);
            }
        }
    }

    __syncthreads();
    float* scr = (float*)(smem + AT_Q);
    if (tid >= 128) {
        const int t = tid - 128;
#pragma unroll
        for (int mt = 0; mt < 2; mt++) {
#pragma unroll
            for (int nt = 0; nt < 8; nt++)
#pragma unroll
                for (int c = 0; c < 4; c++)
                    scr[t * 69 + (mt * 8 + nt) * 4 + c] = acc_pv[mt][nt][c];
            scr[t * 69 + 64 + mt * 2]     = acc_den[mt][0];
            scr[t * 69 + 64 + mt * 2 + 1] = acc_den[mt][2];
        }
    }
    __syncthreads();
    if (tid < 128) {
#pragma unroll
        for (int mt = 0; mt < 2; mt++) {
            const int rl = wm + mt * 16 + (lane >> 2);
            const float den0 = acc_den[mt][0] + scr[tid * 69 + 64 + mt * 2];
            const float den1 = acc_den[mt][2] + scr[tid * 69 + 64 + mt * 2 + 1];
            const float inv0 = __fdividef(1.0f, den0 + 1e-4f);
            const float inv1 = __fdividef(1.0f, den1 + 1e-4f);
            const int l = l0 + rl;
#pragma unroll
            for (int nt = 0; nt < 8; nt++) {
                const int c = nt * 8 + 2 * (lane & 3);
                const int si = tid * 69 + (mt * 8 + nt) * 4;
                const float o0 = (acc_pv[mt][nt][0] + scr[si + 0]) * inv0;
                const float o1 = (acc_pv[mt][nt][1] + scr[si + 1]) * inv0;
                const float o2 = (acc_pv[mt][nt][2] + scr[si + 2]) * inv1;
                const float o3 = (acc_pv[mt][nt][3] + scr[si + 3]) * inv1;
                *(half2*)&g_ctxh[(size_t)(l * BATCH + b) * EMB + h * HD + c] =
                    __floats2half2_rn(o0, o1);
                *(half2*)&g_ctxh[(size_t)((l + 8) * BATCH + b) * EMB + h * HD + c] =
                    __floats2half2_rn(o2, o3);
            }
        }
    }
}

// =====================================================================
// avg_weights from fp16 attn: grid 4096, 256 thr
// =====================================================================
__global__ __launch_bounds__(256) void k_avg_h(float* __restrict__ outAvg)
{
    const size_t t = (size_t)blockIdx.x * 256 + threadIdx.x;
    const int s8 = (int)(t & (SK / 8 - 1));
    const int l  = (int)((t >> 8) & (LQ - 1));
    const int b  = (int)(t >> 19);
    float acc[8] = {0, 0, 0, 0, 0, 0, 0, 0};
#pragma unroll
    for (int h = 0; h < NH; h++) {
        const uint4 u = *(const uint4*)&g_attnh[((size_t)(b * NH + h) * LQ + l) * SK + s8 * 8];
        const half2* p = (const half2*)&u;
#pragma unroll
        for (int j = 0; j < 4; j++) {
            const float2 f = __half22float2(p[j]);
            acc[2 * j]     += f.x;
            acc[2 * j + 1] += f.y;
        }
    }
    float* o = outAvg + t * 8;
    const float inv = 1.0f / NH;
    *(float4*)o       = make_float4(acc[0] * inv, acc[1] * inv, acc[2] * inv, acc[3] * inv);
    *(float4*)(o + 4) = make_float4(acc[4] * inv, acc[5] * inv, acc[6] * inv, acc[7] * inv);
}

// =====================================================================
extern "C" void kernel_launch(void* const* d_in, const int* in_sizes, int n_in,
                              void* d_out, int out_size)
{
    (void)in_sizes; (void)n_in; (void)out_size;
    const float* q    = (const float*)d_in[0];
    const float* k    = (const float*)d_in[1];
    const float* v    = (const float*)d_in[2];
    const float* Wqkv = (const float*)d_in[3];
    const float* bqkv = (const float*)d_in[4];
    const float* Wo   = (const float*)d_in[5];
    const float* bo   = (const float*)d_in[6];
    float* out    = (float*)d_out;
    float* outAvg = out + (size_t)LQ * BATCH * EMB;

    // lazily created once (first call = correctness run, NOT during capture)
    static cudaStream_t s2 = nullptr;
    static cudaEvent_t ev0 = nullptr, evW = nullptr, evA = nullptr, evB = nullptr;
    if (s2 == nullptr) {
        cudaStreamCreateWithFlags(&s2, cudaStreamNonBlocking);
        cudaEventCreateWithFlags(&ev0, cudaEventDisableTiming);
        cudaEventCreateWithFlags(&evW, cudaEventDisableTiming);
        cudaEventCreateWithFlags(&evA, cudaEventDisableTiming);
        cudaEventCreateWithFlags(&evB, cudaEventDisableTiming);
        cudaFuncSetAttribute(k_inproj_cp,  cudaFuncAttributeMaxDynamicSharedMemorySize, PROJ_SMEM);
        cudaFuncSetAttribute(k_outproj_cp, cudaFuncAttributeMaxDynamicSharedMemorySize, PROJ_SMEM);
        cudaFuncSetAttribute(k_attn,       cudaFuncAttributeMaxDynamicSharedMemorySize, ATTN_SMEM);
    }

    __half* inh; __half* wh; __half* woh;
    cudaGetSymbolAddress((void**)&inh, g_inh);
    cudaGetSymbolAddress((void**)&wh,  g_wh);
    cudaGetSymbolAddress((void**)&woh, g_woh);

    const int nIn = MR * EMB / 8;          // 524288
    const int nW  = 3 * EMB * EMB / 8;     // 393216
    const int nWo = EMB * EMB / 8;         // 131072

    // fork: s2 handles weight conversions concurrently with input conversion
    cudaEventRecord(ev0, 0);
    cudaStreamWaitEvent(s2, ev0, 0);
    k_f2h<<<(nW + 255) / 256, 256, 0, s2>>>(Wqkv, wh, nW);
    k_f2h<<<(nWo + 255) / 256, 256, 0, s2>>>(Wo, woh, nWo);
    cudaEventRecord(evW, s2);

    k_f2h3<<<dim3((nIn + 255) / 256, 3), 256>>>(q, k, v, inh, nIn);
    cudaStreamWaitEvent(0, evW, 0);   // inproj needs g_wh

    k_inproj_cp<<<dim3(EMB / 128, MR / 256, 3), 256, PROJ_SMEM>>>(bqkv);
    k_attn<<<dim3(LQ / 128, BHn), 256, ATTN_SMEM>>>();
    cudaEventRecord(evA, 0);

    // fork after attn: avg (DRAM-bound) runs concurrently with outproj
    cudaStreamWaitEvent(s2, evA, 0);
    k_avg_h<<<4096, 256, 0, s2>>>(outAvg);
    cudaEventRecord(evB, s2);

    k_outproj_cp<<<dim3(EMB / 128, MR / 256), 256, PROJ_SMEM>>>(bo, out);
    cudaStreamWaitEvent(0, evB, 0);   // join before harness reads d_out
}

// round 16
// speedup vs baseline: 1.1941x; 1.0155x over previous
#include <cuda_runtime.h>
#include <cuda_fp16.h>
#include <math.h>
#include <stdint.h>

// Problem constants
#define LQ    2048
#define BATCH 2
#define EMB   1024
#define NH    16
#define HD    64
#define SK    2048
#define BHn   32
#define MR    4096

// ---------------- scratch (device globals) ----------------
__device__ __half g_inh[3 * MR * EMB];
__device__ __half g_wh[3 * EMB * EMB];
__device__ __half g_woh[EMB * EMB];
__device__ __half g_qh[BHn * LQ * HD];              // pre-scaled 1/16
__device__ __half g_kh[BHn * SK * HD];
__device__ __half g_vth[BHn * HD * SK];
__device__ __half g_attnh[(size_t)BHn * LQ * SK];
__device__ __half g_ctxh[MR * EMB];

// ---------------- helpers ----------------
__device__ __forceinline__ uint32_t f2h2(float a, float b) {
    half2 h = __floats2half2_rn(a, b);
    return *reinterpret_cast<uint32_t*>(&h);
}
__device__ __forceinline__ uint32_t smem_u32(const void* p) {
    return (uint32_t)__cvta_generic_to_shared(p);
}

#define LDSM4(R0,R1,R2,R3,ADDR) \
    asm volatile("ldmatrix.sync.aligned.m8n8.x4.shared.b16 {%0,%1,%2,%3}, [%4];" \
        : "=r"(R0), "=r"(R1), "=r"(R2), "=r"(R3) : "r"(ADDR))

#define MMAH(C,A,B0,B1) \
    asm volatile("mma.sync.aligned.m16n8k16.row.col.f32.f16.f16.f32 " \
        "{%0,%1,%2,%3},{%4,%5,%6,%7},{%8,%9},{%0,%1,%2,%3};" \
        : "+f"((C)[0]), "+f"((C)[1]), "+f"((C)[2]), "+f"((C)[3]) \
        : "r"((A)[0]), "r"((A)[1]), "r"((A)[2]), "r"((A)[3]), "r"(B0), "r"(B1))

#define CPA16(DST, SRC) \
    asm volatile("cp.async.ca.shared.global [%0], [%1], 16;" \
        :: "r"(DST), "l"(SRC) : "memory")
#define CPA_COMMIT() asm volatile("cp.async.commit_group;" ::: "memory")
#define CPA_WAIT0()  asm volatile("cp.async.wait_group 0;" ::: "memory")

// bulk copy: one full 128B row, completion via mbarrier tx bytes
#define BULK128(DST, SRC, MB) \
    asm volatile("cp.async.bulk.shared::cluster.global.mbarrier::complete_tx::bytes " \
        "[%0], [%1], 128, [%2];" :: "r"(DST), "l"(SRC), "r"(MB) : "memory")

#define MB_INIT(MB, CNT) \
    asm volatile("mbarrier.init.shared.b64 [%0], %1;" :: "r"(MB), "r"((uint32_t)(CNT)) : "memory")
#define MB_EXPECT(MB, BYTES) \
    asm volatile("mbarrier.arrive.expect_tx.shared.b64 _, [%0], %1;" \
        :: "r"(MB), "r"((uint32_t)(BYTES)) : "memory")

#define MBAR_WAIT(mb, par) do { \
    uint32_t _m = (mb), _p = (par), _d; \
    asm volatile("{\n\t.reg .pred p;\n\t" \
        "mbarrier.try_wait.parity.acquire.cta.shared::cta.b64 p, [%1], %2;\n\t" \
        "selp.b32 %0, 1, 0, p;\n\t}" : "=r"(_d) : "r"(_m), "r"(_p) : "memory"); \
    if (!_d) { \
        asm volatile("{\n\t.reg .pred P1;\n\t" \
            "WL_%=:\n\t" \
            "mbarrier.try_wait.parity.acquire.cta.shared::cta.b64 P1, [%0], %1, 0x989680;\n\t" \
            "@P1 bra.uni WD_%=;\n\t" \
            "bra.uni WL_%=;\n\t" \
            "WD_%=:\n\t}" :: "r"(_m), "r"(_p) : "memory"); \
    } \
} while (0)

#define BARG(ID) asm volatile("bar.sync %0, 128;" :: "r"(ID) : "memory")

// sigmoid(2u): 0.5*tanh(u)+0.5 (Q pre-scaled by extra 0.5)
__device__ __forceinline__ uint32_t sig_h2(float a, float b) {
    uint32_t p = f2h2(a, b);
    asm("tanh.approx.f16x2 %0, %0;" : "+r"(p));
    const half2 H05 = __half2half2(__ushort_as_half(0x3800));
    half2 t = *reinterpret_cast<half2*>(&p);
    t = __hfma2(t, H05, H05);
    return *reinterpret_cast<uint32_t*>(&t);
}

// =====================================================================
// fp32 -> fp16 conversion kernels
// =====================================================================
__global__ __launch_bounds__(256) void k_f2h3(
    const float* __restrict__ s0, const float* __restrict__ s1,
    const float* __restrict__ s2, __half* __restrict__ d, int n8)
{
    const float* s = (blockIdx.y == 0) ? s0 : (blockIdx.y == 1) ? s1 : s2;
    __half* dp = d + (size_t)blockIdx.y * n8 * 8;
    const int i = blockIdx.x * 256 + threadIdx.x;
    if (i < n8) {
        const float4 a = ((const float4*)s)[2 * i];
        const float4 b = ((const float4*)s)[2 * i + 1];
        uint4 o;
        o.x = f2h2(a.x, a.y); o.y = f2h2(a.z, a.w);
        o.z = f2h2(b.x, b.y); o.w = f2h2(b.z, b.w);
        ((uint4*)dp)[i] = o;
    }
}

__global__ __launch_bounds__(256) void k_f2h(const float* __restrict__ s,
                                             __half* __restrict__ d, int n8)
{
    const int i = blockIdx.x * 256 + threadIdx.x;
    if (i < n8) {
        const float4 a = ((const float4*)s)[2 * i];
        const float4 b = ((const float4*)s)[2 * i + 1];
        uint4 o;
        o.x = f2h2(a.x, a.y); o.y = f2h2(a.z, a.w);
        o.z = f2h2(b.x, b.y); o.w = f2h2(b.z, b.w);
        ((uint4*)d)[i] = o;
    }
}

// =====================================================================
// BULK-staged GEMM core 256x128: 256 thr, 8 warps (4m x 2n), warp 64x64,
// BK=64, 2-stage. Rows staged whole via cp.async.bulk (128B) into
// linear 144B-stride smem (conflict-free ldmatrix, no swizzle).
// smem: mb @0 (16B) | A0 @1024 (36864) | A1 @37888 | B0 @74752 (18432)
//       | B1 @93184.  Total 111616.
// =====================================================================
#define PJ_A    1024
#define PJ_ASTG 36864
#define PJ_B    74752
#define PJ_BSTG 18432
#define PROJ_SMEM 111616

__device__ __forceinline__ void gemm_blk256(
    const __half* __restrict__ A, int lda,
    const __half* __restrict__ B, int ldb,
    int K, float (&acc)[4][8][4], char* smem)
{
    const uint32_t sb = smem_u32(smem);
    const int tid = threadIdx.x, lane = tid & 31, warp = tid >> 5;
    const int wm0 = (warp >> 1) * 64, wn0 = (warp & 1) * 64;

    if (tid == 0) { MB_INIT(sb + 0, 256); MB_INIT(sb + 8, 256); }
    __syncthreads();

    const __half* Ap = A + (size_t)tid * lda;              // A row tid (0..255)
    const __half* Bp = B + (size_t)(tid & 127) * ldb;      // B row tid&127
    const uint32_t aDst = sb + PJ_A + (uint32_t)tid * 144;
    const uint32_t bDst = sb + PJ_B + (uint32_t)(tid & 127) * 144;
    const uint32_t myBytes = (tid < 128) ? 256u : 128u;

#define BLK_ISSUE(t, s) do { \
        const uint32_t _mb = sb + (uint32_t)((s) * 8); \
        MB_EXPECT(_mb, myBytes); \
        BULK128(aDst + (uint32_t)((s) * PJ_ASTG), Ap + (t) * 64, _mb); \
        if (tid < 128) BULK128(bDst + (uint32_t)((s) * PJ_BSTG), Bp + (t) * 64, _mb); \
    } while (0)

    const int arow = wm0 + (lane & 15), agh = lane >> 4;
    const int brow = wn0 + (lane & 7) + ((lane >> 4) << 3), bgh = (lane >> 3) & 1;
    const uint32_t aB0 = sb + PJ_A + (uint32_t)arow * 144;
    const uint32_t bB0 = sb + PJ_B + (uint32_t)brow * 144;

#pragma unroll
    for (int mt = 0; mt < 4; mt++)
#pragma unroll
        for (int nt = 0; nt < 8; nt++)
#pragma unroll
            for (int c = 0; c < 4; c++) acc[mt][nt][c] = 0.0f;

    BLK_ISSUE(0, 0);

    const int iters = K >> 6;
    for (int it = 0; it < iters; it++) {
        MBAR_WAIT(sb + (uint32_t)((it & 1) * 8), (it >> 1) & 1);
        __syncthreads();

        if (it + 1 < iters) BLK_ISSUE(it + 1, (it + 1) & 1);

        const uint32_t aB = aB0 + (uint32_t)((it & 1) * PJ_ASTG);
        const uint32_t bB = bB0 + (uint32_t)((it & 1) * PJ_BSTG);
#pragma unroll
        for (int ss = 0; ss < 4; ss++) {
            const uint32_t offA = (uint32_t)((2 * ss + agh) << 4);
            const uint32_t offB = (uint32_t)((2 * ss + bgh) << 4);
            uint32_t af[4][4], bf[4][4];
#pragma unroll
            for (int mt = 0; mt < 4; mt++)
                LDSM4(af[mt][0], af[mt][1], af[mt][2], af[mt][3],
                      aB + (uint32_t)(mt * 2304) + offA);
#pragma unroll
            for (int bt = 0; bt < 4; bt++)
                LDSM4(bf[bt][0], bf[bt][1], bf[bt][2], bf[bt][3],
                      bB + (uint32_t)(bt * 2304) + offB);
#pragma unroll
            for (int mt = 0; mt < 4; mt++)
#pragma unroll
                for (int bt = 0; bt < 4; bt++) {
                    MMAH(acc[mt][2 * bt],     af[mt], bf[bt][0], bf[bt][1]);
                    MMAH(acc[mt][2 * bt + 1], af[mt], bf[bt][2], bf[bt][3]);
                }
        }
    }
#undef BLK_ISSUE
}

// =====================================================================
// in-projection: grid (8, 16, 3), 256 thr, CTA tile 256x128.
// =====================================================================
__global__ __launch_bounds__(256, 1) void k_inproj_cp(const float* __restrict__ bias)
{
    extern __shared__ char smem[];
    const int p = blockIdx.z;
    const int m0 = blockIdx.y * 256, n0 = blockIdx.x * 128;
    const __half* A = g_inh + (size_t)p * MR * EMB + (size_t)m0 * EMB;
    const __half* B = g_wh + (size_t)p * EMB * EMB + (size_t)n0 * EMB;
    const float* bp = bias + p * EMB;
    const float scale = (p == 0) ? 0.0625f : 1.0f;

    float acc[4][8][4];
    gemm_blk256(A, EMB, B, EMB, EMB, acc, smem);

    const int lane = threadIdx.x & 31, warp = threadIdx.x >> 5;
    const int wm0 = (warp >> 1) * 64, wn0 = (warp & 1) * 64;

    if (p == 2) {
        __syncthreads();
        __half* ts = (__half*)smem;
        const int STR = 130;
#pragma unroll
        for (int nt = 0; nt < 8; nt++) {
            const int c = wn0 + nt * 8 + 2 * (lane & 3);
            const float b0 = bp[n0 + c], b1 = bp[n0 + c + 1];
#pragma unroll
            for (int mt = 0; mt < 4; mt++) {
                const int r = wm0 + mt * 16 + (lane >> 2);
                *(half2*)&ts[r * STR + c] =
                    __floats2half2_rn(acc[mt][nt][0] + b0, acc[mt][nt][1] + b1);
                *(half2*)&ts[(r + 8) * STR + c] =
                    __floats2half2_rn(acc[mt][nt][2] + b0, acc[mt][nt][3] + b1);
            }
        }
        __syncthreads();
        const int t = threadIdx.x;
        {
            const int col = t & 127;
            const int bb  = t >> 7;
            const int hg  = (n0 >> 6) + (col >> 6);
            const int d   = col & 63;
            __half buf[128];
#pragma unroll
            for (int li = 0; li < 128; li++)
                buf[li] = ts[(2 * li + bb) * STR + col];
            __half* dst = g_vth + ((size_t)(bb * NH + hg) * HD + d) * SK + (m0 >> 1);
#pragma unroll
            for (int g = 0; g < 16; g++)
                *(uint4*)(dst + g * 8) = *(uint4*)(buf + g * 8);
        }
        return;
    }

    __syncthreads();
    __half* ts = (__half*)smem;
    const int STR = 136;
#pragma unroll
    for (int nt = 0; nt < 8; nt++) {
        const int c = wn0 + nt * 8 + 2 * (lane & 3);
        const float b0 = bp[n0 + c], b1 = bp[n0 + c + 1];
#pragma unroll
        for (int mt = 0; mt < 4; mt++) {
            const int r = wm0 + mt * 16 + (lane >> 2);
            *(half2*)&ts[r * STR + c] =
                __floats2half2_rn((acc[mt][nt][0] + b0) * scale,
                                  (acc[mt][nt][1] + b1) * scale);
            *(half2*)&ts[(r + 8) * STR + c] =
                __floats2half2_rn((acc[mt][nt][2] + b0) * scale,
                                  (acc[mt][nt][3] + b1) * scale);
        }
    }
    __syncthreads();
    {
        const int t = threadIdx.x;
        const int l = (m0 + t) >> 1, bb = (m0 + t) & 1;
#pragma unroll
        for (int hh = 0; hh < 2; hh++) {
            const int hg = (n0 >> 6) + hh;
            const int bh = bb * NH + hg;
            uint4 buf[8];
#pragma unroll
            for (int g = 0; g < 8; g++)
                buf[g] = *(uint4*)&ts[t * STR + hh * 64 + g * 8];
            __half* dst = (p == 0 ? g_qh : g_kh) + ((size_t)bh * LQ + l) * HD;
#pragma unroll
            for (int g = 0; g < 8; g++)
                *(uint4*)(dst + g * 8) = buf[g];
        }
    }
}

// =====================================================================
// out-projection: grid (8, 16), 256 thr, CTA tile 256x128.
// =====================================================================
__global__ __launch_bounds__(256, 1) void k_outproj_cp(
    const float* __restrict__ bo, float* __restrict__ out)
{
    extern __shared__ char smem[];
    const int m0 = blockIdx.y * 256, n0 = blockIdx.x * 128;

    float acc[4][8][4];
    gemm_blk256(g_ctxh + (size_t)m0 * EMB, EMB, g_woh + (size_t)n0 * EMB, EMB, EMB, acc, smem);

    const int lane = threadIdx.x & 31, warp = threadIdx.x >> 5;
    const int wm0 = (warp >> 1) * 64, wn0 = (warp & 1) * 64;

#pragma unroll
    for (int nt = 0; nt < 8; nt++) {
        const int c = n0 + wn0 + nt * 8 + 2 * (lane & 3);
        const float b0 = bo[c], b1 = bo[c + 1];
#pragma unroll
        for (int mt = 0; mt < 4; mt++) {
            const int r = m0 + wm0 + mt * 16 + (lane >> 2);
            *(float2*)&out[(size_t)r * EMB + c] =
                make_float2(acc[mt][nt][0] + b0, acc[mt][nt][1] + b1);
            *(float2*)&out[(size_t)(r + 8) * EMB + c] =
                make_float2(acc[mt][nt][2] + b0, acc[mt][nt][3] + b1);
        }
    }
}

// =====================================================================
// FUSED attention: CTA = (128 l-rows, bh), 256 thr = 2 groups x 4 warps,
// warp 32m x 64s, register-direct P, P@ones denoms, named barriers.
// K/V staged via cp.async.bulk rows into 144B-stride smem (per-group
// mbarrier pipeline); Q staged once via cp.async.
// smem: mb @0 (32B: g*16+s*8) | Q @1024 (128x144=18432) |
//       group g @19456+g*36864: K0|K1 (9216 each) | V0|V1
// =====================================================================
#define AT_Q    1024
#define AT_G0   19456
#define AT_GSZ  36864
#define AT_KSTG 9216
#define AT_VOFF 18432
#define ATTN_SMEM (AT_G0 + 2 * AT_GSZ)   // 93184

__global__ __launch_bounds__(256, 1) void k_attn()
{
    extern __shared__ char smem[];
    const uint32_t sb = smem_u32(smem);

    const int bh = blockIdx.y;
    const int l0 = blockIdx.x * 128;
    const int b = bh >> 4, h = bh & 15;
    const int tid = threadIdx.x, lane = tid & 31, warp = tid >> 5;
    const int wg = warp >> 2;
    const int wl = warp & 3;
    const int wm = wl * 32;
    const uint32_t gb = AT_G0 + (uint32_t)wg * AT_GSZ;
    const int lt = tid & 127;
    const int barid = 1 + wg;
    const uint32_t ONES = 0x3C003C00u;

    if (tid == 0) {
        MB_INIT(sb + 0, 128);  MB_INIT(sb + 8, 128);
        MB_INIT(sb + 16, 128); MB_INIT(sb + 24, 128);
    }
    __syncthreads();
    const uint32_t mb0 = sb + (uint32_t)(wg * 16);

    // ---- Q staging (cp.async, linear 144-stride) ----
    {
        const int qr = tid >> 1, qg = (tid & 1) * 4;
        const __half* qs = g_qh + ((size_t)bh * LQ + l0 + qr) * HD + qg * 8;
        const uint32_t qd = sb + AT_Q + (uint32_t)qr * 144 + (uint32_t)qg * 16;
#pragma unroll
        for (int gi = 0; gi < 4; gi++)
            CPA16(qd + (uint32_t)(gi * 16), qs + gi * 8);
        CPA_COMMIT();
    }

    // ---- K/V bulk staging: thread lt<64 -> K row lt; else V row lt-64 ----
    const bool isV = lt >= 64;
    const int kvr = lt & 63;
    const __half* ksrc0 = g_kh + ((size_t)bh * SK + (size_t)wg * 64 + kvr) * HD;
    const __half* vsrc0 = g_vth + ((size_t)bh * HD + kvr) * SK + wg * 64;
    const uint32_t kvDst = gb + (isV ? AT_VOFF : 0u) + (uint32_t)kvr * 144;

#define AT_ISSUE(t, s) do { \
        const uint32_t _mb = mb0 + (uint32_t)((s) * 8); \
        MB_EXPECT(_mb, 128u); \
        if (isV) BULK128(sb + kvDst + (uint32_t)((s) * AT_KSTG), vsrc0 + (size_t)(t) * 128, _mb); \
        else     BULK128(sb + kvDst + (uint32_t)((s) * AT_KSTG), ksrc0 + (size_t)(t) * 128 * HD, _mb); \
    } while (0)

    AT_ISSUE(0, 0);

    const int aRow = wm + (lane & 15), agh = lane >> 4;
    const int bRow = (lane & 7) + ((lane >> 4) << 3), bgh = (lane >> 3) & 1;
    const uint32_t aQ  = sb + AT_Q + (uint32_t)aRow * 144;
    const uint32_t bK0 = sb + gb + (uint32_t)bRow * 144;
    const uint32_t bV0 = bK0 + AT_VOFF;

    float acc_pv[2][8][4], acc_den[2][4];
#pragma unroll
    for (int mt = 0; mt < 2; mt++) {
#pragma unroll
        for (int c = 0; c < 4; c++) acc_den[mt][c] = 0.0f;
#pragma unroll
        for (int nt = 0; nt < 8; nt++)
#pragma unroll
            for (int c = 0; c < 4; c++) acc_pv[mt][nt][c] = 0.0f;
    }

    const int r0b = wm + (lane >> 2);
    const int c0b = 2 * (lane & 3);

    for (int it = 0; it < 16; it++) {
        MBAR_WAIT(mb0 + (uint32_t)((it & 1) * 8), (it >> 1) & 1);
        if (it == 0) { CPA_WAIT0(); __syncthreads(); }
        else BARG(barid);

        if (it < 15) AT_ISSUE(it + 1, (it + 1) & 1);

        const uint32_t so = (uint32_t)((it & 1) * AT_KSTG);
        const uint32_t bK = bK0 + so, bV = bV0 + so;

        // ---- QK^T ----
        float acc_qk[2][8][4];
#pragma unroll
        for (int mt = 0; mt < 2; mt++)
#pragma unroll
            for (int nt = 0; nt < 8; nt++)
#pragma unroll
                for (int c = 0; c < 4; c++) acc_qk[mt][nt][c] = 0.0f;

#pragma unroll
        for (int ss = 0; ss < 4; ss++) {
            const uint32_t offA = (uint32_t)((2 * ss + agh) << 4);
            const uint32_t offB = (uint32_t)((2 * ss + bgh) << 4);
            uint32_t af[2][4], bf[4][4];
#pragma unroll
            for (int mt = 0; mt < 2; mt++)
                LDSM4(af[mt][0], af[mt][1], af[mt][2], af[mt][3],
                      aQ + (uint32_t)(mt * 2304) + offA);
#pragma unroll
            for (int bt = 0; bt < 4; bt++)
                LDSM4(bf[bt][0], bf[bt][1], bf[bt][2], bf[bt][3],
                      bK + (uint32_t)(bt * 2304) + offB);
#pragma unroll
            for (int mt = 0; mt < 2; mt++)
#pragma unroll
                for (int bt = 0; bt < 4; bt++) {
                    MMAH(acc_qk[mt][2 * bt],     af[mt], bf[bt][0], bf[bt][1]);
                    MMAH(acc_qk[mt][2 * bt + 1], af[mt], bf[bt][2], bf[bt][3]);
                }
        }

        // ---- sigmoid: register-direct pack + attn STG ----
        const int s0 = (2 * it + wg) * 64;
        uint32_t pa[2][4][4];
#pragma unroll
        for (int mt = 0; mt < 2; mt++) {
            const int r0 = r0b + mt * 16;
            __half* ar0 = g_attnh + ((size_t)bh * LQ + l0 + r0) * SK + s0 + c0b;
            __half* ar1 = ar0 + 8 * SK;
#pragma unroll
            for (int nt = 0; nt < 8; nt++) {
                const uint32_t p01 = sig_h2(acc_qk[mt][nt][0], acc_qk[mt][nt][1]);
                const uint32_t p23 = sig_h2(acc_qk[mt][nt][2], acc_qk[mt][nt][3]);
                *(uint32_t*)(ar0 + nt * 8) = p01;
                *(uint32_t*)(ar1 + nt * 8) = p23;
                pa[mt][nt >> 1][(nt & 1) ? 2 : 0] = p01;
                pa[mt][nt >> 1][(nt & 1) ? 3 : 1] = p23;
            }
        }

        // ---- P @ V^T (A from registers) + P @ ones ----
#pragma unroll
        for (int ss = 0; ss < 4; ss++) {
            const uint32_t offB = (uint32_t)((2 * ss + bgh) << 4);
            uint32_t bf[4][4];
#pragma unroll
            for (int bt = 0; bt < 4; bt++)
                LDSM4(bf[bt][0], bf[bt][1], bf[bt][2], bf[bt][3],
                      bV + (uint32_t)(bt * 2304) + offB);
#pragma unroll
            for (int mt = 0; mt < 2; mt++) {
#pragma unroll
                for (int bt = 0; bt < 4; bt++) {
                    MMAH(acc_pv[mt][2 * bt],     pa[mt][ss], bf[bt][0], bf[bt][1]);
                    MMAH(acc_pv[mt][2 * bt + 1], pa[mt][ss], bf[bt][2], bf[bt][3]);
                }
                MMAH(acc_den[mt], pa[mt][ss], ONES, ONES);
            }
        }
    }
#undef AT_ISSUE

    // ---- cross-group merge (scratch reuses Q/K area) ----
    __syncthreads();
    float* scr = (float*)(smem + AT_Q);
    if (tid >= 128) {
        const int t = tid - 128;
#pragma unroll
        for (int mt = 0; mt < 2; mt++) {
#pragma unroll
            for (int nt = 0; nt < 8; nt++)
#pragma unroll
                for (int c = 0; c < 4; c++)
                    scr[t * 69 + (mt * 8 + nt) * 4 + c] = acc_pv[mt][nt][c];
            scr[t * 69 + 64 + mt * 2]     = acc_den[mt][0];
            scr[t * 69 + 64 + mt * 2 + 1] = acc_den[mt][2];
        }
    }
    __syncthreads();
    if (tid < 128) {
#pragma unroll
        for (int mt = 0; mt < 2; mt++) {
            const int rl = wm + mt * 16 + (lane >> 2);
            const float den0 = acc_den[mt][0] + scr[tid * 69 + 64 + mt * 2];
            const float den1 = acc_den[mt][2] + scr[tid * 69 + 64 + mt * 2 + 1];
            const float inv0 = __fdividef(1.0f, den0 + 1e-4f);
            const float inv1 = __fdividef(1.0f, den1 + 1e-4f);
            const int l = l0 + rl;
#pragma unroll
            for (int nt = 0; nt < 8; nt++) {
                const int c = nt * 8 + 2 * (lane & 3);
                const int si = tid * 69 + (mt * 8 + nt) * 4;
                const float o0 = (acc_pv[mt][nt][0] + scr[si + 0]) * inv0;
                const float o1 = (acc_pv[mt][nt][1] + scr[si + 1]) * inv0;
                const float o2 = (acc_pv[mt][nt][2] + scr[si + 2]) * inv1;
                const float o3 = (acc_pv[mt][nt][3] + scr[si + 3]) * inv1;
                *(half2*)&g_ctxh[(size_t)(l * BATCH + b) * EMB + h * HD + c] =
                    __floats2half2_rn(o0, o1);
                *(half2*)&g_ctxh[(size_t)((l + 8) * BATCH + b) * EMB + h * HD + c] =
                    __floats2half2_rn(o2, o3);
            }
        }
    }
}

// =====================================================================
// avg_weights from fp16 attn: grid 4096, 256 thr
// =====================================================================
__global__ __launch_bounds__(256) void k_avg_h(float* __restrict__ outAvg)
{
    const size_t t = (size_t)blockIdx.x * 256 + threadIdx.x;
    const int s8 = (int)(t & (SK / 8 - 1));
    const int l  = (int)((t >> 8) & (LQ - 1));
    const int b  = (int)(t >> 19);
    float acc[8] = {0, 0, 0, 0, 0, 0, 0, 0};
#pragma unroll
    for (int h = 0; h < NH; h++) {
        const uint4 u = *(const uint4*)&g_attnh[((size_t)(b * NH + h) * LQ + l) * SK + s8 * 8];
        const half2* p = (const half2*)&u;
#pragma unroll
        for (int j = 0; j < 4; j++) {
            const float2 f = __half22float2(p[j]);
            acc[2 * j]     += f.x;
            acc[2 * j + 1] += f.y;
        }
    }
    float* o = outAvg + t * 8;
    const float inv = 1.0f / NH;
    *(float4*)o       = make_float4(acc[0] * inv, acc[1] * inv, acc[2] * inv, acc[3] * inv);
    *(float4*)(o + 4) = make_float4(acc[4] * inv, acc[5] * inv, acc[6] * inv, acc[7] * inv);
}

// =====================================================================
extern "C" void kernel_launch(void* const* d_in, const int* in_sizes, int n_in,
                              void* d_out, int out_size)
{
    (void)in_sizes; (void)n_in; (void)out_size;
    const float* q    = (const float*)d_in[0];
    const float* k    = (const float*)d_in[1];
    const float* v    = (const float*)d_in[2];
    const float* Wqkv = (const float*)d_in[3];
    const float* bqkv = (const float*)d_in[4];
    const float* Wo   = (const float*)d_in[5];
    const float* bo   = (const float*)d_in[6];
    float* out    = (float*)d_out;
    float* outAvg = out + (size_t)LQ * BATCH * EMB;

    static cudaStream_t s2 = nullptr;
    static cudaEvent_t ev0 = nullptr, evW = nullptr, evA = nullptr, evB = nullptr;
    if (s2 == nullptr) {
        cudaStreamCreateWithFlags(&s2, cudaStreamNonBlocking);
        cudaEventCreateWithFlags(&ev0, cudaEventDisableTiming);
        cudaEventCreateWithFlags(&evW, cudaEventDisableTiming);
        cudaEventCreateWithFlags(&evA, cudaEventDisableTiming);
        cudaEventCreateWithFlags(&evB, cudaEventDisableTiming);
        cudaFuncSetAttribute(k_inproj_cp,  cudaFuncAttributeMaxDynamicSharedMemorySize, PROJ_SMEM);
        cudaFuncSetAttribute(k_outproj_cp, cudaFuncAttributeMaxDynamicSharedMemorySize, PROJ_SMEM);
        cudaFuncSetAttribute(k_attn,       cudaFuncAttributeMaxDynamicSharedMemorySize, ATTN_SMEM);
    }

    __half* inh; __half* wh; __half* woh;
    cudaGetSymbolAddress((void**)&inh, g_inh);
    cudaGetSymbolAddress((void**)&wh,  g_wh);
    cudaGetSymbolAddress((void**)&woh, g_woh);

    const int nIn = MR * EMB / 8;
    const int nW  = 3 * EMB * EMB / 8;
    const int nWo = EMB * EMB / 8;

    cudaEventRecord(ev0, 0);
    cudaStreamWaitEvent(s2, ev0, 0);
    k_f2h<<<(nW + 255) / 256, 256, 0, s2>>>(Wqkv, wh, nW);
    k_f2h<<<(nWo + 255) / 256, 256, 0, s2>>>(Wo, woh, nWo);
    cudaEventRecord(evW, s2);

    k_f2h3<<<dim3((nIn + 255) / 256, 3), 256>>>(q, k, v, inh, nIn);
    cudaStreamWaitEvent(0, evW, 0);

    k_inproj_cp<<<dim3(EMB / 128, MR / 256, 3), 256, PROJ_SMEM>>>(bqkv);
    k_attn<<<dim3(LQ / 128, BHn), 256, ATTN_SMEM>>>();
    cudaEventRecord(evA, 0);

    cudaStreamWaitEvent(s2, evA, 0);
    k_avg_h<<<4096, 256, 0, s2>>>(outAvg);
    cudaEventRecord(evB, s2);

    k_outproj_cp<<<dim3(EMB / 128, MR / 256), 256, PROJ_SMEM>>>(bo, out);
    cudaStreamWaitEvent(0, evB, 0);
}